// round 1
// baseline (speedup 1.0000x reference)
#include <cuda_runtime.h>
#include <cmath>
#include <cstdint>

#define Bv 4
#define Tv 2048
#define Cv 1024
#define Hv 16
#define Dv 64
#define GM (Bv*Tv)      // 8192
#define GK Cv           // 1024
#define GN (3*Cv)       // 3072
#define SSTR 68

// Scratch for Q, K, V in [B,H,T,D] layout (32 MB each) — static device arrays,
// no runtime allocation.
__device__ float g_Q[Bv*Hv*Tv*Dv];
__device__ float g_K[Bv*Hv*Tv*Dv];
__device__ float g_V[Bv*Hv*Tv*Dv];

__device__ __forceinline__ float tf32r(float x) {
    unsigned u;
    asm("cvt.rna.tf32.f32 %0, %1;" : "=r"(u) : "f"(x));
    return __uint_as_float(u);
}

__device__ __forceinline__ void mma_tf32(float* c, const unsigned* a, unsigned b0, unsigned b1) {
    asm volatile(
        "mma.sync.aligned.m16n8k8.row.col.f32.tf32.tf32.f32 "
        "{%0,%1,%2,%3}, {%4,%5,%6,%7}, {%8,%9}, {%0,%1,%2,%3};\n"
        : "+f"(c[0]), "+f"(c[1]), "+f"(c[2]), "+f"(c[3])
        : "r"(a[0]), "r"(a[1]), "r"(a[2]), "r"(a[3]), "r"(b0), "r"(b1));
}

// ---------------------------------------------------------------------------
// Kernel 1: QKV projection GEMM.  X[8192,1024] @ W[1024,3072] -> scatter into
// g_Q/g_K/g_V as [B,H,T,D].  Block tile 128x128, k-tile 16, 8 warps (4m x 2n),
// warp tile 32x64, tf32 m16n8k8.
// ---------------------------------------------------------------------------
__global__ __launch_bounds__(256) void qkv_gemm_kernel(const float* __restrict__ X,
                                                       const float* __restrict__ W) {
    __shared__ float sA[128][20];    // pad 4: conflict-free A-frag LDS
    __shared__ float sB[16][136];    // pad 8: conflict-free B-frag LDS

    const int tid  = threadIdx.x;
    const int lane = tid & 31;
    const int wid  = tid >> 5;
    const int wm   = wid & 3;        // warp m index 0..3
    const int wn   = wid >> 2;       // warp n index 0..1
    const int m0   = blockIdx.y * 128;
    const int n0   = blockIdx.x * 128;

    const int arow = tid >> 2;            // 0..63
    const int acol = (tid & 3) << 2;      // 0,4,8,12
    const int brow = tid >> 5;            // 0..7
    const int bcol = (tid & 31) << 2;     // 0..124

    const float* Abase = X + (size_t)(m0 + arow) * GK + acol;
    const float* Bbase = W + (size_t)brow * GN + n0 + bcol;

    float4 ra[2], rb[2];
    #pragma unroll
    for (int p = 0; p < 2; p++) {
        ra[p] = *(const float4*)(Abase + (size_t)p * 64 * GK);
        rb[p] = *(const float4*)(Bbase + (size_t)p * 8 * GN);
    }

    float acc[2][8][4];
    #pragma unroll
    for (int i = 0; i < 2; i++)
        #pragma unroll
        for (int j = 0; j < 8; j++)
            #pragma unroll
            for (int k = 0; k < 4; k++) acc[i][j][k] = 0.f;

    for (int kt = 0; kt < GK/16; kt++) {
        // stage prefetched regs to smem (tf32-rounded once here)
        #pragma unroll
        for (int p = 0; p < 2; p++) {
            float4 v = ra[p];
            int r = arow + p*64;
            sA[r][acol+0] = tf32r(v.x);
            sA[r][acol+1] = tf32r(v.y);
            sA[r][acol+2] = tf32r(v.z);
            sA[r][acol+3] = tf32r(v.w);
            float4 w = rb[p];
            int r2 = brow + p*8;
            sB[r2][bcol+0] = tf32r(w.x);
            sB[r2][bcol+1] = tf32r(w.y);
            sB[r2][bcol+2] = tf32r(w.z);
            sB[r2][bcol+3] = tf32r(w.w);
        }
        __syncthreads();

        // prefetch next k-tile while computing this one
        if (kt < GK/16 - 1) {
            #pragma unroll
            for (int p = 0; p < 2; p++) {
                ra[p] = *(const float4*)(Abase + (size_t)p * 64 * GK + (size_t)(kt+1)*16);
                rb[p] = *(const float4*)(Bbase + ((size_t)p * 8 + (size_t)(kt+1)*16) * GN);
            }
        }

        #pragma unroll
        for (int ks = 0; ks < 2; ks++) {
            const int kb = ks * 8;
            unsigned af[2][4];
            unsigned bf[8][2];
            #pragma unroll
            for (int mf = 0; mf < 2; mf++) {
                int r = wm*32 + mf*16 + (lane >> 2);
                int c = kb + (lane & 3);
                af[mf][0] = __float_as_uint(sA[r  ][c  ]);
                af[mf][1] = __float_as_uint(sA[r+8][c  ]);
                af[mf][2] = __float_as_uint(sA[r  ][c+4]);
                af[mf][3] = __float_as_uint(sA[r+8][c+4]);
            }
            #pragma unroll
            for (int nf = 0; nf < 8; nf++) {
                int cn = wn*64 + nf*8 + (lane >> 2);
                bf[nf][0] = __float_as_uint(sB[kb + (lane & 3)    ][cn]);
                bf[nf][1] = __float_as_uint(sB[kb + (lane & 3) + 4][cn]);
            }
            #pragma unroll
            for (int mf = 0; mf < 2; mf++)
                #pragma unroll
                for (int nf = 0; nf < 8; nf++)
                    mma_tf32(acc[mf][nf], af[mf], bf[nf][0], bf[nf][1]);
        }
        __syncthreads();
    }

    // Epilogue: scatter to Q/K/V in [B,H,T,D]
    #pragma unroll
    for (int mf = 0; mf < 2; mf++) {
        #pragma unroll
        for (int rr = 0; rr < 2; rr++) {
            int m  = m0 + wm*32 + mf*16 + (lane >> 2) + rr*8;
            int bb = m >> 11;            // / T
            int tt = m & (Tv - 1);
            #pragma unroll
            for (int nf = 0; nf < 8; nf++) {
                int n  = n0 + wn*64 + nf*8 + ((lane & 3) << 1);
                int s  = n >> 10;        // 0:q 1:k 2:v
                int cc = n & (Cv - 1);
                int h  = cc >> 6;
                int d  = cc & 63;
                float* dst = (s == 0) ? g_Q : ((s == 1) ? g_K : g_V);
                size_t off = (((size_t)(bb*Hv + h))*Tv + tt)*Dv + d;
                float2 v2 = make_float2(acc[mf][nf][rr*2+0], acc[mf][nf][rr*2+1]);
                *(float2*)(dst + off) = v2;
            }
        }
    }
}

// ---------------------------------------------------------------------------
// Kernel 2: causal flash attention over [B,H,T,D] scratch.
// Block = one (b,h, 64-query tile).  4 warps, each owns 16 query rows.
// BKV = 64, online softmax in fp32, tf32 mma for QK^T and PV.
// ---------------------------------------------------------------------------
__global__ __launch_bounds__(128) void attn_kernel(float* __restrict__ out) {
    extern __shared__ float sm[];
    float* sK  = sm;                    // [64][SSTR] key-major
    float* sVt = sm + 64*SSTR;          // [64][SSTR] d-major (transposed V)
    float* sPQ = sm + 2*64*SSTR;        // [64][SSTR] Q tile then P tiles

    const int tid  = threadIdx.x;
    const int lane = tid & 31;
    const int wid  = tid >> 5;
    const int bh   = blockIdx.y;                       // b*H + h
    const int qt   = (Tv/64 - 1) - blockIdx.x;         // heavy tiles first
    const float scale = 0.125f;                        // D^-0.5

    const float* Qg = g_Q + (size_t)bh * Tv * Dv;
    const float* Kg = g_K + (size_t)bh * Tv * Dv;
    const float* Vg = g_V + (size_t)bh * Tv * Dv;

    // stage Q tile (tf32-rounded)
    {
        int r  = tid >> 1;
        int c0 = (tid & 1) * 32;
        const float4* src = (const float4*)(Qg + (size_t)(qt*64 + r)*Dv + c0);
        #pragma unroll
        for (int i = 0; i < 8; i++) {
            float4 v = src[i];
            float* d = &sPQ[r*SSTR + c0 + i*4];
            d[0]=tf32r(v.x); d[1]=tf32r(v.y); d[2]=tf32r(v.z); d[3]=tf32r(v.w);
        }
    }
    __syncthreads();

    // Q A-fragments live in registers for the whole kv loop
    unsigned qf[8][4];
    {
        int r = wid*16 + (lane >> 2);
        #pragma unroll
        for (int kt = 0; kt < 8; kt++) {
            int c = kt*8 + (lane & 3);
            qf[kt][0] = __float_as_uint(sPQ[ r   *SSTR + c    ]);
            qf[kt][1] = __float_as_uint(sPQ[(r+8)*SSTR + c    ]);
            qf[kt][2] = __float_as_uint(sPQ[ r   *SSTR + c + 4]);
            qf[kt][3] = __float_as_uint(sPQ[(r+8)*SSTR + c + 4]);
        }
    }

    float o[8][4];
    #pragma unroll
    for (int i = 0; i < 8; i++)
        #pragma unroll
        for (int j = 0; j < 4; j++) o[i][j] = 0.f;
    float mrow[2] = {-INFINITY, -INFINITY};
    float lrow[2] = {0.f, 0.f};

    for (int j = 0; j <= qt; j++) {
        __syncthreads();   // protect sK/sVt reuse from previous iteration
        // stage K (key-major) and V (transposed, d-major)
        {
            int r  = tid >> 1;
            int c0 = (tid & 1) * 32;
            const float4* ks = (const float4*)(Kg + (size_t)(j*64 + r)*Dv + c0);
            const float4* vs = (const float4*)(Vg + (size_t)(j*64 + r)*Dv + c0);
            #pragma unroll
            for (int i = 0; i < 8; i++) {
                float4 v = ks[i];
                float* dk = &sK[r*SSTR + c0 + i*4];
                dk[0]=tf32r(v.x); dk[1]=tf32r(v.y); dk[2]=tf32r(v.z); dk[3]=tf32r(v.w);
                float4 w = vs[i];
                int dd = c0 + i*4;
                sVt[(dd+0)*SSTR + r] = tf32r(w.x);
                sVt[(dd+1)*SSTR + r] = tf32r(w.y);
                sVt[(dd+2)*SSTR + r] = tf32r(w.z);
                sVt[(dd+3)*SSTR + r] = tf32r(w.w);
            }
        }
        __syncthreads();

        // S = Q K^T   (warp tile 16x64)
        float s[8][4];
        #pragma unroll
        for (int i = 0; i < 8; i++)
            #pragma unroll
            for (int k = 0; k < 4; k++) s[i][k] = 0.f;
        #pragma unroll
        for (int kt = 0; kt < 8; kt++) {
            #pragma unroll
            for (int nf = 0; nf < 8; nf++) {
                int key = nf*8 + (lane >> 2);
                int dd  = kt*8 + (lane & 3);
                unsigned b0 = __float_as_uint(sK[key*SSTR + dd    ]);
                unsigned b1 = __float_as_uint(sK[key*SSTR + dd + 4]);
                mma_tf32(s[nf], qf[kt], b0, b1);
            }
        }

        // scale + causal mask + online softmax
        const bool diag = (j == qt);
        float mnew[2], alpha[2];
        #pragma unroll
        for (int rr = 0; rr < 2; rr++) {
            float mx = -INFINITY;
            #pragma unroll
            for (int nf = 0; nf < 8; nf++) {
                #pragma unroll
                for (int cc = 0; cc < 2; cc++) {
                    float v = s[nf][rr*2+cc] * scale;
                    if (diag) {
                        int qrow = wid*16 + (lane >> 2) + rr*8;
                        int kcol = nf*8 + ((lane & 3) << 1) + cc;
                        if (kcol > qrow) v = -INFINITY;
                    }
                    s[nf][rr*2+cc] = v;
                    mx = fmaxf(mx, v);
                }
            }
            mx = fmaxf(mx, __shfl_xor_sync(0xffffffffu, mx, 1));
            mx = fmaxf(mx, __shfl_xor_sync(0xffffffffu, mx, 2));
            float mn = fmaxf(mrow[rr], mx);
            mnew[rr]  = mn;
            alpha[rr] = __expf(mrow[rr] - mn);
            mrow[rr]  = mn;
        }
        float rs[2] = {0.f, 0.f};
        #pragma unroll
        for (int nf = 0; nf < 8; nf++) {
            #pragma unroll
            for (int rr = 0; rr < 2; rr++) {
                #pragma unroll
                for (int cc = 0; cc < 2; cc++) {
                    float p = __expf(s[nf][rr*2+cc] - mnew[rr]);
                    s[nf][rr*2+cc] = p;
                    rs[rr] += p;
                }
            }
        }
        #pragma unroll
        for (int rr = 0; rr < 2; rr++) {
            float r2 = rs[rr];
            r2 += __shfl_xor_sync(0xffffffffu, r2, 1);
            r2 += __shfl_xor_sync(0xffffffffu, r2, 2);
            lrow[rr] = lrow[rr]*alpha[rr] + r2;
            #pragma unroll
            for (int nf = 0; nf < 8; nf++) {
                o[nf][rr*2+0] *= alpha[rr];
                o[nf][rr*2+1] *= alpha[rr];
            }
        }

        // P -> smem (tf32), warp-private rows, then PV mma
        #pragma unroll
        for (int rr = 0; rr < 2; rr++) {
            int r = wid*16 + (lane >> 2) + rr*8;
            #pragma unroll
            for (int nf = 0; nf < 8; nf++) {
                int c = nf*8 + ((lane & 3) << 1);
                float2 pv;
                pv.x = tf32r(s[nf][rr*2+0]);
                pv.y = tf32r(s[nf][rr*2+1]);
                *(float2*)(&sPQ[r*SSTR + c]) = pv;
            }
        }
        __syncwarp();

        #pragma unroll
        for (int kt = 0; kt < 8; kt++) {
            unsigned pa[4];
            int r = wid*16 + (lane >> 2);
            int c = kt*8 + (lane & 3);
            pa[0] = __float_as_uint(sPQ[ r   *SSTR + c    ]);
            pa[1] = __float_as_uint(sPQ[(r+8)*SSTR + c    ]);
            pa[2] = __float_as_uint(sPQ[ r   *SSTR + c + 4]);
            pa[3] = __float_as_uint(sPQ[(r+8)*SSTR + c + 4]);
            #pragma unroll
            for (int nf = 0; nf < 8; nf++) {
                int key0 = kt*8 + (lane & 3);
                int dd   = nf*8 + (lane >> 2);
                unsigned b0 = __float_as_uint(sVt[dd*SSTR + key0    ]);
                unsigned b1 = __float_as_uint(sVt[dd*SSTR + key0 + 4]);
                mma_tf32(o[nf], pa, b0, b1);
            }
        }
    }

    // normalize + write out[b][t][h*64+d]
    const int b = bh >> 4;
    const int h = bh & 15;
    #pragma unroll
    for (int rr = 0; rr < 2; rr++) {
        float inv = 1.0f / lrow[rr];
        int q = qt*64 + wid*16 + (lane >> 2) + rr*8;
        float* dst = out + ((size_t)b*Tv + q)*Cv + h*Dv;
        #pragma unroll
        for (int nf = 0; nf < 8; nf++) {
            int dd = nf*8 + ((lane & 3) << 1);
            float2 v2;
            v2.x = o[nf][rr*2+0] * inv;
            v2.y = o[nf][rr*2+1] * inv;
            *(float2*)(dst + dd) = v2;
        }
    }
}

extern "C" void kernel_launch(void* const* d_in, const int* in_sizes, int n_in,
                              void* d_out, int out_size) {
    const float* x = (const float*)d_in[0];     // [B,T,C] fp32
    const float* w = (const float*)d_in[1];     // [C,3C] fp32
    float* out = (float*)d_out;                 // [B,T,C] fp32

    dim3 ggrid(GN/128, GM/128);                 // (24, 64)
    qkv_gemm_kernel<<<ggrid, 256>>>(x, w);

    const int smem = 3 * 64 * SSTR * (int)sizeof(float);   // 52224 B
    cudaFuncSetAttribute(attn_kernel, cudaFuncAttributeMaxDynamicSharedMemorySize, smem);
    attn_kernel<<<dim3(Tv/64, Bv*Hv), 128, smem>>>(out);
}

// round 7
// speedup vs baseline: 1.0278x; 1.0278x over previous
#include <cuda_runtime.h>
#include <cmath>
#include <cstdint>

#define Bv 4
#define Tv 2048
#define Cv 1024
#define Hv 16
#define Dv 64
#define GM (Bv*Tv)      // 8192
#define GK Cv           // 1024
#define GN (3*Cv)       // 3072
#define SSTR 68

// Scratch for Q, K, V in [B,H,T,D] layout — 96 MiB total, matching the
// proven-passing R1 footprint.  NO other device statics.
__device__ __align__(16) float g_Q[Bv*Hv*Tv*Dv];
__device__ __align__(16) float g_K[Bv*Hv*Tv*Dv];
__device__ __align__(16) float g_V[Bv*Hv*Tv*Dv];

__device__ __forceinline__ float tf32r(float x) {
    unsigned u;
    asm("cvt.rna.tf32.f32 %0, %1;" : "=r"(u) : "f"(x));
    return __uint_as_float(u);
}

__device__ __forceinline__ void mma_tf32(float* c, const unsigned* a, unsigned b0, unsigned b1) {
    asm volatile(
        "mma.sync.aligned.m16n8k8.row.col.f32.tf32.tf32.f32 "
        "{%0,%1,%2,%3}, {%4,%5,%6,%7}, {%8,%9}, {%0,%1,%2,%3};\n"
        : "+f"(c[0]), "+f"(c[1]), "+f"(c[2]), "+f"(c[3])
        : "r"(a[0]), "r"(a[1]), "r"(a[2]), "r"(a[3]), "r"(b0), "r"(b1));
}

// ---------------------------------------------------------------------------
// Kernel 1: QKV projection GEMM.  X[8192,1024] @ W[1024,3072] -> scatter into
// g_Q/g_K/g_V as [B,H,T,D] (tf32-rounded in the epilogue).
// R1 structure + double-buffered smem => ONE __syncthreads per k-tile.
// Block tile 128x128, k-tile 16, 8 warps (4m x 2n), warp tile 32x64.
// ---------------------------------------------------------------------------
__global__ __launch_bounds__(256) void qkv_gemm_kernel(const float* __restrict__ X,
                                                       const float* __restrict__ W) {
    __shared__ float sA[2][128][20];    // pad 4: conflict-free A-frag LDS
    __shared__ float sB[2][16][136];    // pad 8: conflict-free B-frag LDS

    const int tid  = threadIdx.x;
    const int lane = tid & 31;
    const int wid  = tid >> 5;
    const int wm   = wid & 3;        // warp m index 0..3
    const int wn   = wid >> 2;       // warp n index 0..1
    const int m0   = blockIdx.y * 128;
    const int n0   = blockIdx.x * 128;

    const int arow = tid >> 2;            // 0..63
    const int acol = (tid & 3) << 2;      // 0,4,8,12
    const int brow = tid >> 5;            // 0..7
    const int bcol = (tid & 31) << 2;     // 0..124

    const float* Abase = X + (size_t)(m0 + arow) * GK + acol;
    const float* Bbase = W + (size_t)brow * GN + n0 + bcol;

    float4 ra[2], rb[2];
    #pragma unroll
    for (int p = 0; p < 2; p++) {
        ra[p] = *(const float4*)(Abase + (size_t)p * 64 * GK);
        rb[p] = *(const float4*)(Bbase + (size_t)p * 8 * GN);
    }

    float acc[2][8][4];
    #pragma unroll
    for (int i = 0; i < 2; i++)
        #pragma unroll
        for (int j = 0; j < 8; j++)
            #pragma unroll
            for (int k = 0; k < 4; k++) acc[i][j][k] = 0.f;

    #pragma unroll 1
    for (int kt = 0; kt < GK/16; kt++) {
        const int pb = kt & 1;
        // stage prefetched regs to smem (tf32-rounded here, as in R1)
        #pragma unroll
        for (int p = 0; p < 2; p++) {
            float4 v = ra[p];
            int r = arow + p*64;
            sA[pb][r][acol+0] = tf32r(v.x);
            sA[pb][r][acol+1] = tf32r(v.y);
            sA[pb][r][acol+2] = tf32r(v.z);
            sA[pb][r][acol+3] = tf32r(v.w);
            float4 w = rb[p];
            int r2 = brow + p*8;
            sB[pb][r2][bcol+0] = tf32r(w.x);
            sB[pb][r2][bcol+1] = tf32r(w.y);
            sB[pb][r2][bcol+2] = tf32r(w.z);
            sB[pb][r2][bcol+3] = tf32r(w.w);
        }
        __syncthreads();

        // prefetch next k-tile while computing this one
        if (kt < GK/16 - 1) {
            #pragma unroll
            for (int p = 0; p < 2; p++) {
                ra[p] = *(const float4*)(Abase + (size_t)p * 64 * GK + (size_t)(kt+1)*16);
                rb[p] = *(const float4*)(Bbase + ((size_t)p * 8 + (size_t)(kt+1)*16) * GN);
            }
        }

        #pragma unroll
        for (int ks = 0; ks < 2; ks++) {
            const int kb = ks * 8;
            unsigned af[2][4];
            unsigned bf[8][2];
            #pragma unroll
            for (int mf = 0; mf < 2; mf++) {
                int r = wm*32 + mf*16 + (lane >> 2);
                int c = kb + (lane & 3);
                af[mf][0] = __float_as_uint(sA[pb][r  ][c  ]);
                af[mf][1] = __float_as_uint(sA[pb][r+8][c  ]);
                af[mf][2] = __float_as_uint(sA[pb][r  ][c+4]);
                af[mf][3] = __float_as_uint(sA[pb][r+8][c+4]);
            }
            #pragma unroll
            for (int nf = 0; nf < 8; nf++) {
                int cn = wn*64 + nf*8 + (lane >> 2);
                bf[nf][0] = __float_as_uint(sB[pb][kb + (lane & 3)    ][cn]);
                bf[nf][1] = __float_as_uint(sB[pb][kb + (lane & 3) + 4][cn]);
            }
            #pragma unroll
            for (int mf = 0; mf < 2; mf++)
                #pragma unroll
                for (int nf = 0; nf < 8; nf++)
                    mma_tf32(acc[mf][nf], af[mf], bf[nf][0], bf[nf][1]);
        }
    }

    // Epilogue: tf32-round + scatter to Q/K/V in [B,H,T,D]
    #pragma unroll
    for (int mf = 0; mf < 2; mf++) {
        #pragma unroll
        for (int rr = 0; rr < 2; rr++) {
            int m  = m0 + wm*32 + mf*16 + (lane >> 2) + rr*8;
            int bb = m >> 11;            // / T
            int tt = m & (Tv - 1);
            #pragma unroll
            for (int nf = 0; nf < 8; nf++) {
                int n  = n0 + wn*64 + nf*8 + ((lane & 3) << 1);
                int s  = n >> 10;        // 0:q 1:k 2:v
                int cc = n & (Cv - 1);
                int h  = cc >> 6;
                int d  = cc & 63;
                float* dst = (s == 0) ? g_Q : ((s == 1) ? g_K : g_V);
                size_t off = (((size_t)(bb*Hv + h))*Tv + tt)*Dv + d;
                float2 v2;
                v2.x = tf32r(acc[mf][nf][rr*2+0]);
                v2.y = tf32r(acc[mf][nf][rr*2+1]);
                *(float2*)(dst + off) = v2;
            }
        }
    }
}

// ---------------------------------------------------------------------------
// Kernel 2: causal flash attention (R1 layout: 64 queries/CTA, 4 warps,
// 16 queries/warp — proven 127-reg, zero-spill configuration).
// Q/K/V arrive pre-tf32-rounded from the GEMM epilogue => pure-copy staging.
// ---------------------------------------------------------------------------
__global__ __launch_bounds__(128) void attn_kernel(float* __restrict__ out) {
    extern __shared__ float sm[];
    float* sK  = sm;                    // [64][SSTR] key-major
    float* sVt = sm + 64*SSTR;          // [64][SSTR] d-major (transposed V)
    float* sPQ = sm + 2*64*SSTR;        // [64][SSTR] Q tile then P tiles

    const int tid  = threadIdx.x;
    const int lane = tid & 31;
    const int wid  = tid >> 5;
    const int bh   = blockIdx.y;                       // b*H + h
    const int qt   = (Tv/64 - 1) - blockIdx.x;         // heavy tiles first
    const float scale = 0.125f;                        // D^-0.5

    const float* Qg = g_Q + (size_t)bh * Tv * Dv;
    const float* Kg = g_K + (size_t)bh * Tv * Dv;
    const float* Vg = g_V + (size_t)bh * Tv * Dv;

    // stage Q tile (pure copy)
    {
        int r  = tid >> 1;
        int c0 = (tid & 1) * 32;
        const float4* src = (const float4*)(Qg + (size_t)(qt*64 + r)*Dv + c0);
        float4* dst = (float4*)(&sPQ[r*SSTR + c0]);
        #pragma unroll
        for (int i = 0; i < 8; i++) dst[i] = src[i];
    }
    __syncthreads();

    // Q A-fragments live in registers for the whole kv loop
    unsigned qf[8][4];
    {
        int r = wid*16 + (lane >> 2);
        #pragma unroll
        for (int kt = 0; kt < 8; kt++) {
            int c = kt*8 + (lane & 3);
            qf[kt][0] = __float_as_uint(sPQ[ r   *SSTR + c    ]);
            qf[kt][1] = __float_as_uint(sPQ[(r+8)*SSTR + c    ]);
            qf[kt][2] = __float_as_uint(sPQ[ r   *SSTR + c + 4]);
            qf[kt][3] = __float_as_uint(sPQ[(r+8)*SSTR + c + 4]);
        }
    }

    float o[8][4];
    #pragma unroll
    for (int i = 0; i < 8; i++)
        #pragma unroll
        for (int j = 0; j < 4; j++) o[i][j] = 0.f;
    float mrow[2] = {-INFINITY, -INFINITY};
    float lrow[2] = {0.f, 0.f};

    for (int j = 0; j <= qt; j++) {
        __syncthreads();   // protect sK/sVt reuse from previous iteration
        // stage K (key-major) and V (transposed, d-major); pure copies
        {
            int r  = tid >> 1;
            int c0 = (tid & 1) * 32;
            const float4* ks = (const float4*)(Kg + (size_t)(j*64 + r)*Dv + c0);
            const float4* vs = (const float4*)(Vg + (size_t)(j*64 + r)*Dv + c0);
            #pragma unroll
            for (int i = 0; i < 8; i++) {
                *(float4*)(&sK[r*SSTR + c0 + i*4]) = ks[i];
                float4 w = vs[i];
                int dd = c0 + i*4;
                sVt[(dd+0)*SSTR + r] = w.x;
                sVt[(dd+1)*SSTR + r] = w.y;
                sVt[(dd+2)*SSTR + r] = w.z;
                sVt[(dd+3)*SSTR + r] = w.w;
            }
        }
        __syncthreads();

        // S = Q K^T   (warp tile 16x64)
        float s[8][4];
        #pragma unroll
        for (int i = 0; i < 8; i++)
            #pragma unroll
            for (int k = 0; k < 4; k++) s[i][k] = 0.f;
        #pragma unroll
        for (int kt = 0; kt < 8; kt++) {
            #pragma unroll
            for (int nf = 0; nf < 8; nf++) {
                int key = nf*8 + (lane >> 2);
                int dd  = kt*8 + (lane & 3);
                unsigned b0 = __float_as_uint(sK[key*SSTR + dd    ]);
                unsigned b1 = __float_as_uint(sK[key*SSTR + dd + 4]);
                mma_tf32(s[nf], qf[kt], b0, b1);
            }
        }

        // scale + causal mask + online softmax
        const bool diag = (j == qt);
        float mnew[2], alpha[2];
        #pragma unroll
        for (int rr = 0; rr < 2; rr++) {
            float mx = -INFINITY;
            #pragma unroll
            for (int nf = 0; nf < 8; nf++) {
                #pragma unroll
                for (int cc = 0; cc < 2; cc++) {
                    float v = s[nf][rr*2+cc] * scale;
                    if (diag) {
                        int qrow = wid*16 + (lane >> 2) + rr*8;
                        int kcol = nf*8 + ((lane & 3) << 1) + cc;
                        if (kcol > qrow) v = -INFINITY;
                    }
                    s[nf][rr*2+cc] = v;
                    mx = fmaxf(mx, v);
                }
            }
            mx = fmaxf(mx, __shfl_xor_sync(0xffffffffu, mx, 1));
            mx = fmaxf(mx, __shfl_xor_sync(0xffffffffu, mx, 2));
            float mn = fmaxf(mrow[rr], mx);
            mnew[rr]  = mn;
            alpha[rr] = __expf(mrow[rr] - mn);
            mrow[rr]  = mn;
        }
        float rs[2] = {0.f, 0.f};
        #pragma unroll
        for (int nf = 0; nf < 8; nf++) {
            #pragma unroll
            for (int rr = 0; rr < 2; rr++) {
                #pragma unroll
                for (int cc = 0; cc < 2; cc++) {
                    float p = __expf(s[nf][rr*2+cc] - mnew[rr]);
                    s[nf][rr*2+cc] = p;
                    rs[rr] += p;
                }
            }
        }
        #pragma unroll
        for (int rr = 0; rr < 2; rr++) {
            float r2 = rs[rr];
            r2 += __shfl_xor_sync(0xffffffffu, r2, 1);
            r2 += __shfl_xor_sync(0xffffffffu, r2, 2);
            lrow[rr] = lrow[rr]*alpha[rr] + r2;
            #pragma unroll
            for (int nf = 0; nf < 8; nf++) {
                o[nf][rr*2+0] *= alpha[rr];
                o[nf][rr*2+1] *= alpha[rr];
            }
        }

        // P -> smem (tf32), warp-private rows, then PV mma
        #pragma unroll
        for (int rr = 0; rr < 2; rr++) {
            int r = wid*16 + (lane >> 2) + rr*8;
            #pragma unroll
            for (int nf = 0; nf < 8; nf++) {
                int c = nf*8 + ((lane & 3) << 1);
                float2 pv;
                pv.x = tf32r(s[nf][rr*2+0]);
                pv.y = tf32r(s[nf][rr*2+1]);
                *(float2*)(&sPQ[r*SSTR + c]) = pv;
            }
        }
        __syncwarp();

        #pragma unroll
        for (int kt = 0; kt < 8; kt++) {
            unsigned pa[4];
            int r = wid*16 + (lane >> 2);
            int c = kt*8 + (lane & 3);
            pa[0] = __float_as_uint(sPQ[ r   *SSTR + c    ]);
            pa[1] = __float_as_uint(sPQ[(r+8)*SSTR + c    ]);
            pa[2] = __float_as_uint(sPQ[ r   *SSTR + c + 4]);
            pa[3] = __float_as_uint(sPQ[(r+8)*SSTR + c + 4]);
            #pragma unroll
            for (int nf = 0; nf < 8; nf++) {
                int key0 = kt*8 + (lane & 3);
                int dd   = nf*8 + (lane >> 2);
                unsigned b0 = __float_as_uint(sVt[dd*SSTR + key0    ]);
                unsigned b1 = __float_as_uint(sVt[dd*SSTR + key0 + 4]);
                mma_tf32(o[nf], pa, b0, b1);
            }
        }
    }

    // normalize + write out[b][t][h*64+d]
    const int b = bh >> 4;
    const int h = bh & 15;
    #pragma unroll
    for (int rr = 0; rr < 2; rr++) {
        float inv = 1.0f / lrow[rr];
        int q = qt*64 + wid*16 + (lane >> 2) + rr*8;
        float* dst = out + ((size_t)b*Tv + q)*Cv + h*Dv;
        #pragma unroll
        for (int nf = 0; nf < 8; nf++) {
            int dd = nf*8 + ((lane & 3) << 1);
            float2 v2;
            v2.x = o[nf][rr*2+0] * inv;
            v2.y = o[nf][rr*2+1] * inv;
            *(float2*)(dst + dd) = v2;
        }
    }
}

extern "C" void kernel_launch(void* const* d_in, const int* in_sizes, int n_in,
                              void* d_out, int out_size) {
    const float* x = (const float*)d_in[0];     // [B,T,C] fp32
    const float* w = (const float*)d_in[1];     // [C,3C] fp32
    float* out = (float*)d_out;                 // [B,T,C] fp32

    dim3 ggrid(GN/128, GM/128);                 // (24, 64)
    qkv_gemm_kernel<<<ggrid, 256>>>(x, w);

    const int smem = 3 * 64 * SSTR * (int)sizeof(float);   // 52224 B
    cudaFuncSetAttribute(attn_kernel, cudaFuncAttributeMaxDynamicSharedMemorySize, smem);
    attn_kernel<<<dim3(Tv/64, Bv*Hv), 128, smem>>>(out);
}

// round 8
// speedup vs baseline: 1.2601x; 1.2260x over previous
#include <cuda_runtime.h>
#include <cmath>
#include <cstdint>

#define Bv 4
#define Tv 2048
#define Cv 1024
#define Hv 16
#define Dv 64
#define GM (Bv*Tv)      // 8192
#define GK Cv           // 1024
#define GN (3*Cv)       // 3072
#define SSTR 68
#define PSTR 36

// Scratch for Q, K, V in [B,H,T,D] layout — 96 MiB total (proven-passing
// footprint).  NO other device statics.
__device__ __align__(16) float g_Q[Bv*Hv*Tv*Dv];
__device__ __align__(16) float g_K[Bv*Hv*Tv*Dv];
__device__ __align__(16) float g_V[Bv*Hv*Tv*Dv];

__device__ __forceinline__ float tf32r(float x) {
    unsigned u;
    asm("cvt.rna.tf32.f32 %0, %1;" : "=r"(u) : "f"(x));
    return __uint_as_float(u);
}

__device__ __forceinline__ void mma_tf32(float* c, const unsigned* a, unsigned b0, unsigned b1) {
    asm volatile(
        "mma.sync.aligned.m16n8k8.row.col.f32.tf32.tf32.f32 "
        "{%0,%1,%2,%3}, {%4,%5,%6,%7}, {%8,%9}, {%0,%1,%2,%3};\n"
        : "+f"(c[0]), "+f"(c[1]), "+f"(c[2]), "+f"(c[3])
        : "r"(a[0]), "r"(a[1]), "r"(a[2]), "r"(a[3]), "r"(b0), "r"(b1));
}

// ---------------------------------------------------------------------------
// Kernel 1: QKV projection GEMM (R7: double-buffered smem, one sync/k-tile).
// Block tile 128x128, k-tile 16, 8 warps (4m x 2n), warp tile 32x64.
// Epilogue tf32-rounds Q/K/V so attention staging is pure copies.
// ---------------------------------------------------------------------------
__global__ __launch_bounds__(256) void qkv_gemm_kernel(const float* __restrict__ X,
                                                       const float* __restrict__ W) {
    __shared__ float sA[2][128][20];
    __shared__ float sB[2][16][136];

    const int tid  = threadIdx.x;
    const int lane = tid & 31;
    const int wid  = tid >> 5;
    const int wm   = wid & 3;
    const int wn   = wid >> 2;
    const int m0   = blockIdx.y * 128;
    const int n0   = blockIdx.x * 128;

    const int arow = tid >> 2;
    const int acol = (tid & 3) << 2;
    const int brow = tid >> 5;
    const int bcol = (tid & 31) << 2;

    const float* Abase = X + (size_t)(m0 + arow) * GK + acol;
    const float* Bbase = W + (size_t)brow * GN + n0 + bcol;

    float4 ra[2], rb[2];
    #pragma unroll
    for (int p = 0; p < 2; p++) {
        ra[p] = *(const float4*)(Abase + (size_t)p * 64 * GK);
        rb[p] = *(const float4*)(Bbase + (size_t)p * 8 * GN);
    }

    float acc[2][8][4];
    #pragma unroll
    for (int i = 0; i < 2; i++)
        #pragma unroll
        for (int j = 0; j < 8; j++)
            #pragma unroll
            for (int k = 0; k < 4; k++) acc[i][j][k] = 0.f;

    #pragma unroll 1
    for (int kt = 0; kt < GK/16; kt++) {
        const int pb = kt & 1;
        #pragma unroll
        for (int p = 0; p < 2; p++) {
            float4 v = ra[p];
            int r = arow + p*64;
            sA[pb][r][acol+0] = tf32r(v.x);
            sA[pb][r][acol+1] = tf32r(v.y);
            sA[pb][r][acol+2] = tf32r(v.z);
            sA[pb][r][acol+3] = tf32r(v.w);
            float4 w = rb[p];
            int r2 = brow + p*8;
            sB[pb][r2][bcol+0] = tf32r(w.x);
            sB[pb][r2][bcol+1] = tf32r(w.y);
            sB[pb][r2][bcol+2] = tf32r(w.z);
            sB[pb][r2][bcol+3] = tf32r(w.w);
        }
        __syncthreads();

        if (kt < GK/16 - 1) {
            #pragma unroll
            for (int p = 0; p < 2; p++) {
                ra[p] = *(const float4*)(Abase + (size_t)p * 64 * GK + (size_t)(kt+1)*16);
                rb[p] = *(const float4*)(Bbase + ((size_t)p * 8 + (size_t)(kt+1)*16) * GN);
            }
        }

        #pragma unroll
        for (int ks = 0; ks < 2; ks++) {
            const int kb = ks * 8;
            unsigned af[2][4];
            unsigned bf[8][2];
            #pragma unroll
            for (int mf = 0; mf < 2; mf++) {
                int r = wm*32 + mf*16 + (lane >> 2);
                int c = kb + (lane & 3);
                af[mf][0] = __float_as_uint(sA[pb][r  ][c  ]);
                af[mf][1] = __float_as_uint(sA[pb][r+8][c  ]);
                af[mf][2] = __float_as_uint(sA[pb][r  ][c+4]);
                af[mf][3] = __float_as_uint(sA[pb][r+8][c+4]);
            }
            #pragma unroll
            for (int nf = 0; nf < 8; nf++) {
                int cn = wn*64 + nf*8 + (lane >> 2);
                bf[nf][0] = __float_as_uint(sB[pb][kb + (lane & 3)    ][cn]);
                bf[nf][1] = __float_as_uint(sB[pb][kb + (lane & 3) + 4][cn]);
            }
            #pragma unroll
            for (int mf = 0; mf < 2; mf++)
                #pragma unroll
                for (int nf = 0; nf < 8; nf++)
                    mma_tf32(acc[mf][nf], af[mf], bf[nf][0], bf[nf][1]);
        }
    }

    #pragma unroll
    for (int mf = 0; mf < 2; mf++) {
        #pragma unroll
        for (int rr = 0; rr < 2; rr++) {
            int m  = m0 + wm*32 + mf*16 + (lane >> 2) + rr*8;
            int bb = m >> 11;
            int tt = m & (Tv - 1);
            #pragma unroll
            for (int nf = 0; nf < 8; nf++) {
                int n  = n0 + wn*64 + nf*8 + ((lane & 3) << 1);
                int s  = n >> 10;
                int cc = n & (Cv - 1);
                int h  = cc >> 6;
                int d  = cc & 63;
                float* dst = (s == 0) ? g_Q : ((s == 1) ? g_K : g_V);
                size_t off = (((size_t)(bb*Hv + h))*Tv + tt)*Dv + d;
                float2 v2;
                v2.x = tf32r(acc[mf][nf][rr*2+0]);
                v2.y = tf32r(acc[mf][nf][rr*2+1]);
                *(float2*)(dst + off) = v2;
            }
        }
    }
}

// ---------------------------------------------------------------------------
// Kernel 2: causal flash attention, 128 queries per CTA (32 per warp).
// K/V staged 64 keys at a time; S computed in 32-key sub-chunks so the live
// S accumulator is only s[2][4][4] while K/V b-fragments are shared across
// both m16 fragments (halved per-query smem traffic vs 16 q/warp).
// ---------------------------------------------------------------------------
__global__ __launch_bounds__(128) void attn_kernel(float* __restrict__ out) {
    extern __shared__ float sm[];
    float* sQ  = sm;                       // [128][SSTR]
    float* sK  = sm + 128*SSTR;            // [64][SSTR]  key-major
    float* sVt = sm + 192*SSTR;            // [64][SSTR]  d-major (transposed V)
    float* sP  = sm + 256*SSTR;            // [128][PSTR] P sub-chunk (128x32)

    const int tid  = threadIdx.x;
    const int lane = tid & 31;
    const int wid  = tid >> 5;
    const int bh   = blockIdx.y;
    const int qt   = (Tv/128 - 1) - blockIdx.x;           // heavy tiles first
    const float scale = 0.125f;

    const float* Qg = g_Q + (size_t)bh * Tv * Dv;
    const float* Kg = g_K + (size_t)bh * Tv * Dv;
    const float* Vg = g_V + (size_t)bh * Tv * Dv;

    // stage Q tile (pure copy; pre-rounded)
    {
        int c0 = (tid & 1) * 32;
        #pragma unroll
        for (int half = 0; half < 2; half++) {
            int r = (tid >> 1) + half*64;
            const float4* src = (const float4*)(Qg + (size_t)(qt*128 + r)*Dv + c0);
            float4* dst = (float4*)(&sQ[r*SSTR + c0]);
            #pragma unroll
            for (int i = 0; i < 8; i++) dst[i] = src[i];
        }
    }

    float o[2][8][4];
    #pragma unroll
    for (int mf = 0; mf < 2; mf++)
        #pragma unroll
        for (int i = 0; i < 8; i++)
            #pragma unroll
            for (int k = 0; k < 4; k++) o[mf][i][k] = 0.f;
    float mrow[2][2] = {{-INFINITY, -INFINITY}, {-INFINITY, -INFINITY}};
    float lrow[2][2] = {{0.f, 0.f}, {0.f, 0.f}};

    const int jmax = 2*qt + 1;
    #pragma unroll 1
    for (int j = 0; j <= jmax; j++) {
        __syncthreads();   // protect sK/sVt (and initial sQ staging)
        {
            int r  = tid >> 1;
            int c0 = (tid & 1) * 32;
            const float4* ks = (const float4*)(Kg + (size_t)(j*64 + r)*Dv + c0);
            const float4* vs = (const float4*)(Vg + (size_t)(j*64 + r)*Dv + c0);
            #pragma unroll
            for (int i = 0; i < 8; i++) {
                *(float4*)(&sK[r*SSTR + c0 + i*4]) = ks[i];
                float4 w = vs[i];
                int dd = c0 + i*4;
                sVt[(dd+0)*SSTR + r] = w.x;
                sVt[(dd+1)*SSTR + r] = w.y;
                sVt[(dd+2)*SSTR + r] = w.z;
                sVt[(dd+3)*SSTR + r] = w.w;
            }
        }
        __syncthreads();

        const bool maybe_mask = (j >= 2*qt);

        #pragma unroll 1
        for (int sub = 0; sub < 2; sub++) {
            // S = Q K^T for this 32-key sub-chunk; warp tile 32x32
            float s[2][4][4];
            #pragma unroll
            for (int mf = 0; mf < 2; mf++)
                #pragma unroll
                for (int i = 0; i < 4; i++)
                    #pragma unroll
                    for (int k = 0; k < 4; k++) s[mf][i][k] = 0.f;

            #pragma unroll
            for (int kt = 0; kt < 8; kt++) {
                unsigned kb[4][2];
                #pragma unroll
                for (int nf = 0; nf < 4; nf++) {
                    int key = sub*32 + nf*8 + (lane >> 2);
                    int dd  = kt*8 + (lane & 3);
                    kb[nf][0] = __float_as_uint(sK[key*SSTR + dd    ]);
                    kb[nf][1] = __float_as_uint(sK[key*SSTR + dd + 4]);
                }
                #pragma unroll
                for (int mf = 0; mf < 2; mf++) {
                    unsigned qa[4];
                    int r = wid*32 + mf*16 + (lane >> 2);
                    int c = kt*8 + (lane & 3);
                    qa[0] = __float_as_uint(sQ[ r   *SSTR + c    ]);
                    qa[1] = __float_as_uint(sQ[(r+8)*SSTR + c    ]);
                    qa[2] = __float_as_uint(sQ[ r   *SSTR + c + 4]);
                    qa[3] = __float_as_uint(sQ[(r+8)*SSTR + c + 4]);
                    #pragma unroll
                    for (int nf = 0; nf < 4; nf++)
                        mma_tf32(s[mf][nf], qa, kb[nf][0], kb[nf][1]);
                }
            }

            // scale + mask + online softmax for this sub-chunk
            #pragma unroll
            for (int mf = 0; mf < 2; mf++) {
                float mnew[2], alpha[2];
                #pragma unroll
                for (int rr = 0; rr < 2; rr++) {
                    int qrow = qt*128 + wid*32 + mf*16 + (lane >> 2) + rr*8;
                    float mx = -INFINITY;
                    #pragma unroll
                    for (int nf = 0; nf < 4; nf++) {
                        #pragma unroll
                        for (int cc = 0; cc < 2; cc++) {
                            float v = s[mf][nf][rr*2+cc] * scale;
                            if (maybe_mask) {
                                int kcol = j*64 + sub*32 + nf*8 + ((lane & 3) << 1) + cc;
                                if (kcol > qrow) v = -INFINITY;
                            }
                            s[mf][nf][rr*2+cc] = v;
                            mx = fmaxf(mx, v);
                        }
                    }
                    mx = fmaxf(mx, __shfl_xor_sync(0xffffffffu, mx, 1));
                    mx = fmaxf(mx, __shfl_xor_sync(0xffffffffu, mx, 2));
                    float mn = fmaxf(mrow[mf][rr], mx);
                    mnew[rr]  = mn;
                    alpha[rr] = __expf(mrow[mf][rr] - mn);
                    mrow[mf][rr] = mn;
                }
                float rs[2] = {0.f, 0.f};
                #pragma unroll
                for (int nf = 0; nf < 4; nf++) {
                    #pragma unroll
                    for (int rr = 0; rr < 2; rr++) {
                        #pragma unroll
                        for (int cc = 0; cc < 2; cc++) {
                            float p = __expf(s[mf][nf][rr*2+cc] - mnew[rr]);
                            s[mf][nf][rr*2+cc] = p;
                            rs[rr] += p;
                        }
                    }
                }
                #pragma unroll
                for (int rr = 0; rr < 2; rr++) {
                    float r2 = rs[rr];
                    r2 += __shfl_xor_sync(0xffffffffu, r2, 1);
                    r2 += __shfl_xor_sync(0xffffffffu, r2, 2);
                    lrow[mf][rr] = lrow[mf][rr]*alpha[rr] + r2;
                    #pragma unroll
                    for (int nf = 0; nf < 8; nf++) {
                        o[mf][nf][rr*2+0] *= alpha[rr];
                        o[mf][nf][rr*2+1] *= alpha[rr];
                    }
                }
                // P sub-chunk -> smem (tf32), warp-private rows
                #pragma unroll
                for (int rr = 0; rr < 2; rr++) {
                    int r = wid*32 + mf*16 + (lane >> 2) + rr*8;
                    #pragma unroll
                    for (int nf = 0; nf < 4; nf++) {
                        int c = nf*8 + ((lane & 3) << 1);
                        float2 pv;
                        pv.x = tf32r(s[mf][nf][rr*2+0]);
                        pv.y = tf32r(s[mf][nf][rr*2+1]);
                        *(float2*)(&sP[r*PSTR + c]) = pv;
                    }
                }
            }
            __syncwarp();

            // O += P V for this 32-key sub-chunk (V b-frags shared across mf)
            #pragma unroll
            for (int kb4 = 0; kb4 < 4; kb4++) {
                unsigned vb[8][2];
                #pragma unroll
                for (int nb = 0; nb < 8; nb++) {
                    int dd   = nb*8 + (lane >> 2);
                    int key0 = sub*32 + kb4*8 + (lane & 3);
                    vb[nb][0] = __float_as_uint(sVt[dd*SSTR + key0    ]);
                    vb[nb][1] = __float_as_uint(sVt[dd*SSTR + key0 + 4]);
                }
                #pragma unroll
                for (int mf = 0; mf < 2; mf++) {
                    unsigned pa[4];
                    int r = wid*32 + mf*16 + (lane >> 2);
                    int c = kb4*8 + (lane & 3);
                    pa[0] = __float_as_uint(sP[ r   *PSTR + c    ]);
                    pa[1] = __float_as_uint(sP[(r+8)*PSTR + c    ]);
                    pa[2] = __float_as_uint(sP[ r   *PSTR + c + 4]);
                    pa[3] = __float_as_uint(sP[(r+8)*PSTR + c + 4]);
                    #pragma unroll
                    for (int nb = 0; nb < 8; nb++)
                        mma_tf32(o[mf][nb], pa, vb[nb][0], vb[nb][1]);
                }
            }
        }
    }

    // normalize + write out[b][t][h*64+d]
    const int b = bh >> 4;
    const int h = bh & 15;
    #pragma unroll
    for (int mf = 0; mf < 2; mf++) {
        #pragma unroll
        for (int rr = 0; rr < 2; rr++) {
            float inv = 1.0f / lrow[mf][rr];
            int q = qt*128 + wid*32 + mf*16 + (lane >> 2) + rr*8;
            float* dst = out + ((size_t)b*Tv + q)*Cv + h*Dv;
            #pragma unroll
            for (int nf = 0; nf < 8; nf++) {
                int dd = nf*8 + ((lane & 3) << 1);
                float2 v2;
                v2.x = o[mf][nf][rr*2+0] * inv;
                v2.y = o[mf][nf][rr*2+1] * inv;
                *(float2*)(dst + dd) = v2;
            }
        }
    }
}

extern "C" void kernel_launch(void* const* d_in, const int* in_sizes, int n_in,
                              void* d_out, int out_size) {
    const float* x = (const float*)d_in[0];     // [B,T,C] fp32
    const float* w = (const float*)d_in[1];     // [C,3C] fp32
    float* out = (float*)d_out;                 // [B,T,C] fp32

    dim3 ggrid(GN/128, GM/128);
    qkv_gemm_kernel<<<ggrid, 256>>>(x, w);

    const int smem = (256*SSTR + 128*PSTR) * (int)sizeof(float);   // 88064
    cudaFuncSetAttribute(attn_kernel, cudaFuncAttributeMaxDynamicSharedMemorySize, smem);
    attn_kernel<<<dim3(Tv/128, Bv*Hv), 128, smem>>>(out);
}

// round 9
// speedup vs baseline: 1.8366x; 1.4575x over previous
#include <cuda_runtime.h>
#include <cuda_fp16.h>
#include <cmath>
#include <cstdint>

#define Bv 4
#define Tv 2048
#define Cv 1024
#define Hv 16
#define Dv 64
#define GM (Bv*Tv)      // 8192
#define GK Cv           // 1024
#define GN (3*Cv)       // 3072
#define SSH 72          // halves stride: sQ/sK/sV rows (conflict-free LDSM)
#define PSH 40          // halves stride: sP rows

// Scratch for Q, K, V in [B,H,T,D] fp16 — 48 MiB total statics.
__device__ __align__(16) __half g_Q[Bv*Hv*Tv*Dv];
__device__ __align__(16) __half g_K[Bv*Hv*Tv*Dv];
__device__ __align__(16) __half g_V[Bv*Hv*Tv*Dv];

__device__ __forceinline__ float tf32r(float x) {
    unsigned u;
    asm("cvt.rna.tf32.f32 %0, %1;" : "=r"(u) : "f"(x));
    return __uint_as_float(u);
}

__device__ __forceinline__ void mma_tf32(float* c, const unsigned* a, unsigned b0, unsigned b1) {
    asm volatile(
        "mma.sync.aligned.m16n8k8.row.col.f32.tf32.tf32.f32 "
        "{%0,%1,%2,%3}, {%4,%5,%6,%7}, {%8,%9}, {%0,%1,%2,%3};\n"
        : "+f"(c[0]), "+f"(c[1]), "+f"(c[2]), "+f"(c[3])
        : "r"(a[0]), "r"(a[1]), "r"(a[2]), "r"(a[3]), "r"(b0), "r"(b1));
}

__device__ __forceinline__ void mma_f16(float* c, const uint32_t* a, uint32_t b0, uint32_t b1) {
    asm volatile(
        "mma.sync.aligned.m16n8k16.row.col.f32.f16.f16.f32 "
        "{%0,%1,%2,%3}, {%4,%5,%6,%7}, {%8,%9}, {%0,%1,%2,%3};\n"
        : "+f"(c[0]), "+f"(c[1]), "+f"(c[2]), "+f"(c[3])
        : "r"(a[0]), "r"(a[1]), "r"(a[2]), "r"(a[3]), "r"(b0), "r"(b1));
}

__device__ __forceinline__ uint32_t smem_u32(const void* p) {
    uint32_t a;
    asm("{ .reg .u64 t; cvta.to.shared.u64 t, %1; cvt.u32.u64 %0, t; }" : "=r"(a) : "l"(p));
    return a;
}

__device__ __forceinline__ void ldmx4(uint32_t* r, uint32_t addr) {
    asm volatile("ldmatrix.sync.aligned.m8n8.x4.shared.b16 {%0,%1,%2,%3}, [%4];"
        : "=r"(r[0]), "=r"(r[1]), "=r"(r[2]), "=r"(r[3]) : "r"(addr));
}
__device__ __forceinline__ void ldmx4t(uint32_t* r, uint32_t addr) {
    asm volatile("ldmatrix.sync.aligned.m8n8.x4.trans.shared.b16 {%0,%1,%2,%3}, [%4];"
        : "=r"(r[0]), "=r"(r[1]), "=r"(r[2]), "=r"(r[3]) : "r"(addr));
}

// ---------------------------------------------------------------------------
// Kernel 1: QKV projection GEMM (tf32, double-buffered smem, one sync/k-tile).
// Epilogue writes fp16 Q/K/V in [B,H,T,D].
// ---------------------------------------------------------------------------
__global__ __launch_bounds__(256) void qkv_gemm_kernel(const float* __restrict__ X,
                                                       const float* __restrict__ W) {
    __shared__ float sA[2][128][20];
    __shared__ float sB[2][16][136];

    const int tid  = threadIdx.x;
    const int lane = tid & 31;
    const int wid  = tid >> 5;
    const int wm   = wid & 3;
    const int wn   = wid >> 2;
    const int m0   = blockIdx.y * 128;
    const int n0   = blockIdx.x * 128;

    const int arow = tid >> 2;
    const int acol = (tid & 3) << 2;
    const int brow = tid >> 5;
    const int bcol = (tid & 31) << 2;

    const float* Abase = X + (size_t)(m0 + arow) * GK + acol;
    const float* Bbase = W + (size_t)brow * GN + n0 + bcol;

    float4 ra[2], rb[2];
    #pragma unroll
    for (int p = 0; p < 2; p++) {
        ra[p] = *(const float4*)(Abase + (size_t)p * 64 * GK);
        rb[p] = *(const float4*)(Bbase + (size_t)p * 8 * GN);
    }

    float acc[2][8][4];
    #pragma unroll
    for (int i = 0; i < 2; i++)
        #pragma unroll
        for (int j = 0; j < 8; j++)
            #pragma unroll
            for (int k = 0; k < 4; k++) acc[i][j][k] = 0.f;

    #pragma unroll 1
    for (int kt = 0; kt < GK/16; kt++) {
        const int pb = kt & 1;
        #pragma unroll
        for (int p = 0; p < 2; p++) {
            float4 v = ra[p];
            int r = arow + p*64;
            sA[pb][r][acol+0] = tf32r(v.x);
            sA[pb][r][acol+1] = tf32r(v.y);
            sA[pb][r][acol+2] = tf32r(v.z);
            sA[pb][r][acol+3] = tf32r(v.w);
            float4 w = rb[p];
            int r2 = brow + p*8;
            sB[pb][r2][bcol+0] = tf32r(w.x);
            sB[pb][r2][bcol+1] = tf32r(w.y);
            sB[pb][r2][bcol+2] = tf32r(w.z);
            sB[pb][r2][bcol+3] = tf32r(w.w);
        }
        __syncthreads();

        if (kt < GK/16 - 1) {
            #pragma unroll
            for (int p = 0; p < 2; p++) {
                ra[p] = *(const float4*)(Abase + (size_t)p * 64 * GK + (size_t)(kt+1)*16);
                rb[p] = *(const float4*)(Bbase + ((size_t)p * 8 + (size_t)(kt+1)*16) * GN);
            }
        }

        #pragma unroll
        for (int ks = 0; ks < 2; ks++) {
            const int kb = ks * 8;
            unsigned af[2][4];
            unsigned bf[8][2];
            #pragma unroll
            for (int mf = 0; mf < 2; mf++) {
                int r = wm*32 + mf*16 + (lane >> 2);
                int c = kb + (lane & 3);
                af[mf][0] = __float_as_uint(sA[pb][r  ][c  ]);
                af[mf][1] = __float_as_uint(sA[pb][r+8][c  ]);
                af[mf][2] = __float_as_uint(sA[pb][r  ][c+4]);
                af[mf][3] = __float_as_uint(sA[pb][r+8][c+4]);
            }
            #pragma unroll
            for (int nf = 0; nf < 8; nf++) {
                int cn = wn*64 + nf*8 + (lane >> 2);
                bf[nf][0] = __float_as_uint(sB[pb][kb + (lane & 3)    ][cn]);
                bf[nf][1] = __float_as_uint(sB[pb][kb + (lane & 3) + 4][cn]);
            }
            #pragma unroll
            for (int mf = 0; mf < 2; mf++)
                #pragma unroll
                for (int nf = 0; nf < 8; nf++)
                    mma_tf32(acc[mf][nf], af[mf], bf[nf][0], bf[nf][1]);
        }
    }

    // Epilogue: fp16-round + scatter to Q/K/V in [B,H,T,D]
    #pragma unroll
    for (int mf = 0; mf < 2; mf++) {
        #pragma unroll
        for (int rr = 0; rr < 2; rr++) {
            int m  = m0 + wm*32 + mf*16 + (lane >> 2) + rr*8;
            int bb = m >> 11;
            int tt = m & (Tv - 1);
            #pragma unroll
            for (int nf = 0; nf < 8; nf++) {
                int n  = n0 + wn*64 + nf*8 + ((lane & 3) << 1);
                int s  = n >> 10;
                int cc = n & (Cv - 1);
                int h  = cc >> 6;
                int d  = cc & 63;
                __half* dst = (s == 0) ? g_Q : ((s == 1) ? g_K : g_V);
                size_t off = (((size_t)(bb*Hv + h))*Tv + tt)*Dv + d;
                __half2 hv = __floats2half2_rn(acc[mf][nf][rr*2+0], acc[mf][nf][rr*2+1]);
                *(__half2*)(dst + off) = hv;
            }
        }
    }
}

// ---------------------------------------------------------------------------
// Kernel 2: causal flash attention, fp16 operands / fp32 accumulate.
// 128 queries per CTA, 4 warps (32 q/warp), 64-key staging, 32-key S
// sub-chunks.  All fragments via ldmatrix; V loaded with .trans (no
// transposed staging).
// ---------------------------------------------------------------------------
__global__ __launch_bounds__(128) void attn_kernel(float* __restrict__ out) {
    __shared__ __half sQ[128*SSH];
    __shared__ __half sK[64*SSH];
    __shared__ __half sV[64*SSH];
    __shared__ __half sP[128*PSH];

    const int tid  = threadIdx.x;
    const int lane = tid & 31;
    const int wid  = tid >> 5;
    const int bh   = blockIdx.y;
    const int qt   = (Tv/128 - 1) - blockIdx.x;           // heavy tiles first
    const float scale = 0.125f;

    const __half* Qg = g_Q + (size_t)bh * Tv * Dv;
    const __half* Kg = g_K + (size_t)bh * Tv * Dv;
    const __half* Vg = g_V + (size_t)bh * Tv * Dv;

    const uint32_t bQ = smem_u32(sQ);
    const uint32_t bK = smem_u32(sK);
    const uint32_t bV = smem_u32(sV);
    const uint32_t bP = smem_u32(sP);

    // ldmatrix lane decomposition
    const int l7  = lane & 7;
    const int lb3 = (lane >> 3) & 1;
    const int lb4 = (lane >> 4) & 1;

    // stage Q tile: one row per thread (64 halves = 8 uint4)
    {
        const uint4* src = (const uint4*)(Qg + (size_t)(qt*128 + tid)*Dv);
        uint4* dst = (uint4*)(sQ + tid*SSH);
        #pragma unroll
        for (int i = 0; i < 8; i++) dst[i] = src[i];
    }

    float o[2][8][4];
    #pragma unroll
    for (int mf = 0; mf < 2; mf++)
        #pragma unroll
        for (int i = 0; i < 8; i++)
            #pragma unroll
            for (int k = 0; k < 4; k++) o[mf][i][k] = 0.f;
    float mrow[2][2] = {{-INFINITY, -INFINITY}, {-INFINITY, -INFINITY}};
    float lrow[2][2] = {{0.f, 0.f}, {0.f, 0.f}};

    const int jmax = 2*qt + 1;
    #pragma unroll 1
    for (int j = 0; j <= jmax; j++) {
        __syncthreads();   // protect sK/sV (and initial sQ staging)
        // stage K and V tiles: pure copies, [key][d] halves
        {
            int r  = tid >> 1;
            int c0 = (tid & 1) * 32;
            const uint4* ks = (const uint4*)(Kg + (size_t)(j*64 + r)*Dv + c0);
            const uint4* vs = (const uint4*)(Vg + (size_t)(j*64 + r)*Dv + c0);
            uint4* kd = (uint4*)(sK + r*SSH + c0);
            uint4* vd = (uint4*)(sV + r*SSH + c0);
            #pragma unroll
            for (int i = 0; i < 4; i++) { kd[i] = ks[i]; vd[i] = vs[i]; }
        }
        __syncthreads();

        const bool maybe_mask = (j >= 2*qt);

        #pragma unroll 1
        for (int sub = 0; sub < 2; sub++) {
            // ---- S = Q K^T for 32-key sub-chunk (warp tile 32x32) ----
            float s[2][4][4];
            #pragma unroll
            for (int mf = 0; mf < 2; mf++)
                #pragma unroll
                for (int i = 0; i < 4; i++)
                    #pragma unroll
                    for (int k = 0; k < 4; k++) s[mf][i][k] = 0.f;

            #pragma unroll
            for (int kt = 0; kt < 4; kt++) {      // 4 x k16 over d=64
                const int kc = kt*16;
                uint32_t kb[2][4];
                #pragma unroll
                for (int g = 0; g < 2; g++) {
                    int row = sub*32 + g*16 + l7 + 8*lb4;      // key
                    int col = kc + 8*lb3;                       // d
                    ldmx4(kb[g], bK + (uint32_t)(row*SSH + col)*2);
                }
                #pragma unroll
                for (int mf = 0; mf < 2; mf++) {
                    uint32_t qa[4];
                    int row = wid*32 + mf*16 + l7 + 8*lb3;      // q row
                    int col = kc + 8*lb4;                        // d
                    ldmx4(qa, bQ + (uint32_t)(row*SSH + col)*2);
                    #pragma unroll
                    for (int nf = 0; nf < 4; nf++)
                        mma_f16(s[mf][nf], qa, kb[nf>>1][(nf&1)*2], kb[nf>>1][(nf&1)*2+1]);
                }
            }

            // ---- scale + mask + online softmax ----
            #pragma unroll
            for (int mf = 0; mf < 2; mf++) {
                float mnew[2], alpha[2];
                #pragma unroll
                for (int rr = 0; rr < 2; rr++) {
                    int qrow = qt*128 + wid*32 + mf*16 + (lane >> 2) + rr*8;
                    float mx = -INFINITY;
                    #pragma unroll
                    for (int nf = 0; nf < 4; nf++) {
                        #pragma unroll
                        for (int cc = 0; cc < 2; cc++) {
                            float v = s[mf][nf][rr*2+cc] * scale;
                            if (maybe_mask) {
                                int kcol = j*64 + sub*32 + nf*8 + ((lane & 3) << 1) + cc;
                                if (kcol > qrow) v = -INFINITY;
                            }
                            s[mf][nf][rr*2+cc] = v;
                            mx = fmaxf(mx, v);
                        }
                    }
                    mx = fmaxf(mx, __shfl_xor_sync(0xffffffffu, mx, 1));
                    mx = fmaxf(mx, __shfl_xor_sync(0xffffffffu, mx, 2));
                    float mn = fmaxf(mrow[mf][rr], mx);
                    mnew[rr]  = mn;
                    alpha[rr] = __expf(mrow[mf][rr] - mn);
                    mrow[mf][rr] = mn;
                }
                float rs[2] = {0.f, 0.f};
                #pragma unroll
                for (int nf = 0; nf < 4; nf++) {
                    #pragma unroll
                    for (int rr = 0; rr < 2; rr++) {
                        #pragma unroll
                        for (int cc = 0; cc < 2; cc++) {
                            float p = __expf(s[mf][nf][rr*2+cc] - mnew[rr]);
                            s[mf][nf][rr*2+cc] = p;
                            rs[rr] += p;
                        }
                    }
                }
                #pragma unroll
                for (int rr = 0; rr < 2; rr++) {
                    float r2 = rs[rr];
                    r2 += __shfl_xor_sync(0xffffffffu, r2, 1);
                    r2 += __shfl_xor_sync(0xffffffffu, r2, 2);
                    lrow[mf][rr] = lrow[mf][rr]*alpha[rr] + r2;
                    #pragma unroll
                    for (int nf = 0; nf < 8; nf++) {
                        o[mf][nf][rr*2+0] *= alpha[rr];
                        o[mf][nf][rr*2+1] *= alpha[rr];
                    }
                }
                // P sub-chunk -> smem (fp16), warp-private rows
                #pragma unroll
                for (int rr = 0; rr < 2; rr++) {
                    int r = wid*32 + mf*16 + (lane >> 2) + rr*8;
                    #pragma unroll
                    for (int nf = 0; nf < 4; nf++) {
                        __half2 h2 = __floats2half2_rn(s[mf][nf][rr*2+0], s[mf][nf][rr*2+1]);
                        *(__half2*)(sP + r*PSH + nf*8 + ((lane & 3) << 1)) = h2;
                    }
                }
            }
            __syncwarp();

            // ---- O += P V for this 32-key sub-chunk ----
            #pragma unroll
            for (int kt = 0; kt < 2; kt++) {      // 2 x k16 over 32 keys
                const int kc = kt*16;
                uint32_t vb[4][4];
                #pragma unroll
                for (int g = 0; g < 4; g++) {      // d0 = g*16
                    int row = sub*32 + kc + l7 + 8*lb3;   // key (stored row)
                    int col = g*16 + 8*lb4;                // d
                    ldmx4t(vb[g], bV + (uint32_t)(row*SSH + col)*2);
                }
                #pragma unroll
                for (int mf = 0; mf < 2; mf++) {
                    uint32_t pa[4];
                    int row = wid*32 + mf*16 + l7 + 8*lb3;
                    int col = kc + 8*lb4;                  // key within sub
                    ldmx4(pa, bP + (uint32_t)(row*PSH + col)*2);
                    #pragma unroll
                    for (int nb = 0; nb < 8; nb++)
                        mma_f16(o[mf][nb], pa, vb[nb>>1][(nb&1)*2], vb[nb>>1][(nb&1)*2+1]);
                }
            }
        }
    }

    // normalize + write out[b][t][h*64+d]
    const int b = bh >> 4;
    const int h = bh & 15;
    #pragma unroll
    for (int mf = 0; mf < 2; mf++) {
        #pragma unroll
        for (int rr = 0; rr < 2; rr++) {
            float inv = 1.0f / lrow[mf][rr];
            int q = qt*128 + wid*32 + mf*16 + (lane >> 2) + rr*8;
            float* dst = out + ((size_t)b*Tv + q)*Cv + h*Dv;
            #pragma unroll
            for (int nf = 0; nf < 8; nf++) {
                int dd = nf*8 + ((lane & 3) << 1);
                float2 v2;
                v2.x = o[mf][nf][rr*2+0] * inv;
                v2.y = o[mf][nf][rr*2+1] * inv;
                *(float2*)(dst + dd) = v2;
            }
        }
    }
}

extern "C" void kernel_launch(void* const* d_in, const int* in_sizes, int n_in,
                              void* d_out, int out_size) {
    const float* x = (const float*)d_in[0];     // [B,T,C] fp32
    const float* w = (const float*)d_in[1];     // [C,3C] fp32
    float* out = (float*)d_out;                 // [B,T,C] fp32

    dim3 ggrid(GN/128, GM/128);
    qkv_gemm_kernel<<<ggrid, 256>>>(x, w);

    attn_kernel<<<dim3(Tv/128, Bv*Hv), 128>>>(out);
}

// round 10
// speedup vs baseline: 1.9574x; 1.0658x over previous
#include <cuda_runtime.h>
#include <cuda_fp16.h>
#include <cmath>
#include <cstdint>

#define Bv 4
#define Tv 2048
#define Cv 1024
#define Hv 16
#define Dv 64
#define GM (Bv*Tv)      // 8192
#define GK Cv           // 1024
#define GN (3*Cv)       // 3072
#define SSH 72          // halves stride: attn sQ/sK/sV rows
#define PSH 40          // halves stride: attn sP rows
#define ASH 40          // halves stride: gemm A rows (32 k + pad)
#define BSH 136         // halves stride: gemm B rows (128 n + pad)

// Scratch for Q, K, V in [B,H,T,D] fp16 — 48 MiB total statics.
__device__ __align__(16) __half g_Q[Bv*Hv*Tv*Dv];
__device__ __align__(16) __half g_K[Bv*Hv*Tv*Dv];
__device__ __align__(16) __half g_V[Bv*Hv*Tv*Dv];

__device__ __forceinline__ void mma_f16(float* c, const uint32_t* a, uint32_t b0, uint32_t b1) {
    asm volatile(
        "mma.sync.aligned.m16n8k16.row.col.f32.f16.f16.f32 "
        "{%0,%1,%2,%3}, {%4,%5,%6,%7}, {%8,%9}, {%0,%1,%2,%3};\n"
        : "+f"(c[0]), "+f"(c[1]), "+f"(c[2]), "+f"(c[3])
        : "r"(a[0]), "r"(a[1]), "r"(a[2]), "r"(a[3]), "r"(b0), "r"(b1));
}

__device__ __forceinline__ uint32_t smem_u32(const void* p) {
    uint32_t a;
    asm("{ .reg .u64 t; cvta.to.shared.u64 t, %1; cvt.u32.u64 %0, t; }" : "=r"(a) : "l"(p));
    return a;
}

__device__ __forceinline__ void ldmx4(uint32_t* r, uint32_t addr) {
    asm volatile("ldmatrix.sync.aligned.m8n8.x4.shared.b16 {%0,%1,%2,%3}, [%4];"
        : "=r"(r[0]), "=r"(r[1]), "=r"(r[2]), "=r"(r[3]) : "r"(addr));
}
__device__ __forceinline__ void ldmx4t(uint32_t* r, uint32_t addr) {
    asm volatile("ldmatrix.sync.aligned.m8n8.x4.trans.shared.b16 {%0,%1,%2,%3}, [%4];"
        : "=r"(r[0]), "=r"(r[1]), "=r"(r[2]), "=r"(r[3]) : "r"(addr));
}

__device__ __forceinline__ uint32_t h2pack(float a, float b) {
    __half2 h = __floats2half2_rn(a, b);
    return *(uint32_t*)&h;
}

// ---------------------------------------------------------------------------
// Kernel 1: QKV projection GEMM — fp16 operands / fp32 accumulate.
// Block tile 128x128, k-tile 32 (2 x k16), 8 warps (4m x 2n), warp 32x64.
// Double-buffered smem, one sync per k-tile, all fragments via ldmatrix.
// Epilogue writes fp16 Q/K/V in [B,H,T,D].
// ---------------------------------------------------------------------------
__global__ __launch_bounds__(256) void qkv_gemm_kernel(const float* __restrict__ X,
                                                       const float* __restrict__ W) {
    __shared__ __half sA[2][128][ASH];   // [m][k]
    __shared__ __half sB[2][32][BSH];    // [k][n]

    const int tid  = threadIdx.x;
    const int lane = tid & 31;
    const int wid  = tid >> 5;
    const int wm   = wid & 3;
    const int wn   = wid >> 2;
    const int m0   = blockIdx.y * 128;
    const int n0   = blockIdx.x * 128;

    const int l7  = lane & 7;
    const int lb3 = (lane >> 3) & 1;
    const int lb4 = (lane >> 4) & 1;

    // staging decomposition
    const int arow  = tid >> 1;            // 0..127
    const int acol0 = (tid & 1) * 16;      // 0 or 16 (floats)
    const int brow  = tid >> 3;            // 0..31
    const int bcol0 = (tid & 7) * 16;      // 0..112 (floats)

    const float* Abase = X + (size_t)(m0 + arow) * GK + acol0;
    const float* Bbase = W + (size_t)brow * GN + n0 + bcol0;

    const uint32_t bA = smem_u32(sA);
    const uint32_t bB = smem_u32(sB);

    float4 ra[4], rb[4];
    #pragma unroll
    for (int i = 0; i < 4; i++) {
        ra[i] = *(const float4*)(Abase + i*4);
        rb[i] = *(const float4*)(Bbase + i*4);
    }

    float acc[2][8][4];
    #pragma unroll
    for (int i = 0; i < 2; i++)
        #pragma unroll
        for (int j = 0; j < 8; j++)
            #pragma unroll
            for (int k = 0; k < 4; k++) acc[i][j][k] = 0.f;

    #pragma unroll 1
    for (int kt = 0; kt < GK/32; kt++) {
        const int pb = kt & 1;
        // convert + store staged regs to smem (fp32 -> half2 pairs)
        {
            uint4 pa0, pa1;
            pa0.x = h2pack(ra[0].x, ra[0].y); pa0.y = h2pack(ra[0].z, ra[0].w);
            pa0.z = h2pack(ra[1].x, ra[1].y); pa0.w = h2pack(ra[1].z, ra[1].w);
            pa1.x = h2pack(ra[2].x, ra[2].y); pa1.y = h2pack(ra[2].z, ra[2].w);
            pa1.z = h2pack(ra[3].x, ra[3].y); pa1.w = h2pack(ra[3].z, ra[3].w);
            *(uint4*)(&sA[pb][arow][acol0    ]) = pa0;
            *(uint4*)(&sA[pb][arow][acol0 + 8]) = pa1;
            uint4 pb0, pb1;
            pb0.x = h2pack(rb[0].x, rb[0].y); pb0.y = h2pack(rb[0].z, rb[0].w);
            pb0.z = h2pack(rb[1].x, rb[1].y); pb0.w = h2pack(rb[1].z, rb[1].w);
            pb1.x = h2pack(rb[2].x, rb[2].y); pb1.y = h2pack(rb[2].z, rb[2].w);
            pb1.z = h2pack(rb[3].x, rb[3].y); pb1.w = h2pack(rb[3].z, rb[3].w);
            *(uint4*)(&sB[pb][brow][bcol0    ]) = pb0;
            *(uint4*)(&sB[pb][brow][bcol0 + 8]) = pb1;
        }
        __syncthreads();

        // prefetch next k-tile
        if (kt < GK/32 - 1) {
            #pragma unroll
            for (int i = 0; i < 4; i++) {
                ra[i] = *(const float4*)(Abase + (size_t)(kt+1)*32 + i*4);
                rb[i] = *(const float4*)(Bbase + ((size_t)(kt+1)*32) * GN + i*4);
            }
        }

        // compute: 2 x k16
        #pragma unroll
        for (int ks = 0; ks < 2; ks++) {
            const int kk = ks * 16;
            uint32_t af[2][4];
            #pragma unroll
            for (int mf = 0; mf < 2; mf++) {
                int row = wm*32 + mf*16 + l7 + 8*lb3;
                int col = kk + 8*lb4;
                ldmx4(af[mf], bA + (uint32_t)(pb*128*ASH + row*ASH + col)*2);
            }
            uint32_t bf[4][4];
            #pragma unroll
            for (int g = 0; g < 4; g++) {       // n groups of 16
                int row = kk + l7 + 8*lb3;      // k
                int col = wn*64 + g*16 + 8*lb4; // n
                ldmx4t(bf[g], bB + (uint32_t)(pb*32*BSH + row*BSH + col)*2);
            }
            #pragma unroll
            for (int mf = 0; mf < 2; mf++)
                #pragma unroll
                for (int nf = 0; nf < 8; nf++)
                    mma_f16(acc[mf][nf], af[mf], bf[nf>>1][(nf&1)*2], bf[nf>>1][(nf&1)*2+1]);
        }
    }

    // Epilogue: fp16-round + scatter to Q/K/V in [B,H,T,D]
    #pragma unroll
    for (int mf = 0; mf < 2; mf++) {
        #pragma unroll
        for (int rr = 0; rr < 2; rr++) {
            int m  = m0 + wm*32 + mf*16 + (lane >> 2) + rr*8;
            int bb = m >> 11;
            int tt = m & (Tv - 1);
            #pragma unroll
            for (int nf = 0; nf < 8; nf++) {
                int n  = n0 + wn*64 + nf*8 + ((lane & 3) << 1);
                int s  = n >> 10;
                int cc = n & (Cv - 1);
                int h  = cc >> 6;
                int d  = cc & 63;
                __half* dst = (s == 0) ? g_Q : ((s == 1) ? g_K : g_V);
                size_t off = (((size_t)(bb*Hv + h))*Tv + tt)*Dv + d;
                __half2 hv = __floats2half2_rn(acc[mf][nf][rr*2+0], acc[mf][nf][rr*2+1]);
                *(__half2*)(dst + off) = hv;
            }
        }
    }
}

// ---------------------------------------------------------------------------
// Kernel 2: causal flash attention (R9: fp16 operands / fp32 accumulate,
// 128 q/CTA, 32 q/warp, 64-key staging, 32-key S sub-chunks, ldmatrix).
// ---------------------------------------------------------------------------
__global__ __launch_bounds__(128) void attn_kernel(float* __restrict__ out) {
    __shared__ __half sQ[128*SSH];
    __shared__ __half sK[64*SSH];
    __shared__ __half sV[64*SSH];
    __shared__ __half sP[128*PSH];

    const int tid  = threadIdx.x;
    const int lane = tid & 31;
    const int wid  = tid >> 5;
    const int bh   = blockIdx.y;
    const int qt   = (Tv/128 - 1) - blockIdx.x;           // heavy tiles first
    const float scale = 0.125f;

    const __half* Qg = g_Q + (size_t)bh * Tv * Dv;
    const __half* Kg = g_K + (size_t)bh * Tv * Dv;
    const __half* Vg = g_V + (size_t)bh * Tv * Dv;

    const uint32_t bQ = smem_u32(sQ);
    const uint32_t bK = smem_u32(sK);
    const uint32_t bV = smem_u32(sV);
    const uint32_t bP = smem_u32(sP);

    const int l7  = lane & 7;
    const int lb3 = (lane >> 3) & 1;
    const int lb4 = (lane >> 4) & 1;

    // stage Q tile: one row per thread
    {
        const uint4* src = (const uint4*)(Qg + (size_t)(qt*128 + tid)*Dv);
        uint4* dst = (uint4*)(sQ + tid*SSH);
        #pragma unroll
        for (int i = 0; i < 8; i++) dst[i] = src[i];
    }

    float o[2][8][4];
    #pragma unroll
    for (int mf = 0; mf < 2; mf++)
        #pragma unroll
        for (int i = 0; i < 8; i++)
            #pragma unroll
            for (int k = 0; k < 4; k++) o[mf][i][k] = 0.f;
    float mrow[2][2] = {{-INFINITY, -INFINITY}, {-INFINITY, -INFINITY}};
    float lrow[2][2] = {{0.f, 0.f}, {0.f, 0.f}};

    const int jmax = 2*qt + 1;
    #pragma unroll 1
    for (int j = 0; j <= jmax; j++) {
        __syncthreads();
        {
            int r  = tid >> 1;
            int c0 = (tid & 1) * 32;
            const uint4* ks = (const uint4*)(Kg + (size_t)(j*64 + r)*Dv + c0);
            const uint4* vs = (const uint4*)(Vg + (size_t)(j*64 + r)*Dv + c0);
            uint4* kd = (uint4*)(sK + r*SSH + c0);
            uint4* vd = (uint4*)(sV + r*SSH + c0);
            #pragma unroll
            for (int i = 0; i < 4; i++) { kd[i] = ks[i]; vd[i] = vs[i]; }
        }
        __syncthreads();

        const bool maybe_mask = (j >= 2*qt);

        #pragma unroll 1
        for (int sub = 0; sub < 2; sub++) {
            float s[2][4][4];
            #pragma unroll
            for (int mf = 0; mf < 2; mf++)
                #pragma unroll
                for (int i = 0; i < 4; i++)
                    #pragma unroll
                    for (int k = 0; k < 4; k++) s[mf][i][k] = 0.f;

            #pragma unroll
            for (int kt = 0; kt < 4; kt++) {
                const int kc = kt*16;
                uint32_t kb[2][4];
                #pragma unroll
                for (int g = 0; g < 2; g++) {
                    int row = sub*32 + g*16 + l7 + 8*lb4;
                    int col = kc + 8*lb3;
                    ldmx4(kb[g], bK + (uint32_t)(row*SSH + col)*2);
                }
                #pragma unroll
                for (int mf = 0; mf < 2; mf++) {
                    uint32_t qa[4];
                    int row = wid*32 + mf*16 + l7 + 8*lb3;
                    int col = kc + 8*lb4;
                    ldmx4(qa, bQ + (uint32_t)(row*SSH + col)*2);
                    #pragma unroll
                    for (int nf = 0; nf < 4; nf++)
                        mma_f16(s[mf][nf], qa, kb[nf>>1][(nf&1)*2], kb[nf>>1][(nf&1)*2+1]);
                }
            }

            #pragma unroll
            for (int mf = 0; mf < 2; mf++) {
                float mnew[2], alpha[2];
                #pragma unroll
                for (int rr = 0; rr < 2; rr++) {
                    int qrow = qt*128 + wid*32 + mf*16 + (lane >> 2) + rr*8;
                    float mx = -INFINITY;
                    #pragma unroll
                    for (int nf = 0; nf < 4; nf++) {
                        #pragma unroll
                        for (int cc = 0; cc < 2; cc++) {
                            float v = s[mf][nf][rr*2+cc] * scale;
                            if (maybe_mask) {
                                int kcol = j*64 + sub*32 + nf*8 + ((lane & 3) << 1) + cc;
                                if (kcol > qrow) v = -INFINITY;
                            }
                            s[mf][nf][rr*2+cc] = v;
                            mx = fmaxf(mx, v);
                        }
                    }
                    mx = fmaxf(mx, __shfl_xor_sync(0xffffffffu, mx, 1));
                    mx = fmaxf(mx, __shfl_xor_sync(0xffffffffu, mx, 2));
                    float mn = fmaxf(mrow[mf][rr], mx);
                    mnew[rr]  = mn;
                    alpha[rr] = __expf(mrow[mf][rr] - mn);
                    mrow[mf][rr] = mn;
                }
                float rs[2] = {0.f, 0.f};
                #pragma unroll
                for (int nf = 0; nf < 4; nf++) {
                    #pragma unroll
                    for (int rr = 0; rr < 2; rr++) {
                        #pragma unroll
                        for (int cc = 0; cc < 2; cc++) {
                            float p = __expf(s[mf][nf][rr*2+cc] - mnew[rr]);
                            s[mf][nf][rr*2+cc] = p;
                            rs[rr] += p;
                        }
                    }
                }
                #pragma unroll
                for (int rr = 0; rr < 2; rr++) {
                    float r2 = rs[rr];
                    r2 += __shfl_xor_sync(0xffffffffu, r2, 1);
                    r2 += __shfl_xor_sync(0xffffffffu, r2, 2);
                    lrow[mf][rr] = lrow[mf][rr]*alpha[rr] + r2;
                    #pragma unroll
                    for (int nf = 0; nf < 8; nf++) {
                        o[mf][nf][rr*2+0] *= alpha[rr];
                        o[mf][nf][rr*2+1] *= alpha[rr];
                    }
                }
                #pragma unroll
                for (int rr = 0; rr < 2; rr++) {
                    int r = wid*32 + mf*16 + (lane >> 2) + rr*8;
                    #pragma unroll
                    for (int nf = 0; nf < 4; nf++) {
                        __half2 h2 = __floats2half2_rn(s[mf][nf][rr*2+0], s[mf][nf][rr*2+1]);
                        *(__half2*)(sP + r*PSH + nf*8 + ((lane & 3) << 1)) = h2;
                    }
                }
            }
            __syncwarp();

            #pragma unroll
            for (int kt = 0; kt < 2; kt++) {
                const int kc = kt*16;
                uint32_t vb[4][4];
                #pragma unroll
                for (int g = 0; g < 4; g++) {
                    int row = sub*32 + kc + l7 + 8*lb3;
                    int col = g*16 + 8*lb4;
                    ldmx4t(vb[g], bV + (uint32_t)(row*SSH + col)*2);
                }
                #pragma unroll
                for (int mf = 0; mf < 2; mf++) {
                    uint32_t pa[4];
                    int row = wid*32 + mf*16 + l7 + 8*lb3;
                    int col = kc + 8*lb4;
                    ldmx4(pa, bP + (uint32_t)(row*PSH + col)*2);
                    #pragma unroll
                    for (int nb = 0; nb < 8; nb++)
                        mma_f16(o[mf][nb], pa, vb[nb>>1][(nb&1)*2], vb[nb>>1][(nb&1)*2+1]);
                }
            }
        }
    }

    // normalize + write out[b][t][h*64+d]
    const int b = bh >> 4;
    const int h = bh & 15;
    #pragma unroll
    for (int mf = 0; mf < 2; mf++) {
        #pragma unroll
        for (int rr = 0; rr < 2; rr++) {
            float inv = 1.0f / lrow[mf][rr];
            int q = qt*128 + wid*32 + mf*16 + (lane >> 2) + rr*8;
            float* dst = out + ((size_t)b*Tv + q)*Cv + h*Dv;
            #pragma unroll
            for (int nf = 0; nf < 8; nf++) {
                int dd = nf*8 + ((lane & 3) << 1);
                float2 v2;
                v2.x = o[mf][nf][rr*2+0] * inv;
                v2.y = o[mf][nf][rr*2+1] * inv;
                *(float2*)(dst + dd) = v2;
            }
        }
    }
}

extern "C" void kernel_launch(void* const* d_in, const int* in_sizes, int n_in,
                              void* d_out, int out_size) {
    const float* x = (const float*)d_in[0];     // [B,T,C] fp32
    const float* w = (const float*)d_in[1];     // [C,3C] fp32
    float* out = (float*)d_out;                 // [B,T,C] fp32

    dim3 ggrid(GN/128, GM/128);
    qkv_gemm_kernel<<<ggrid, 256>>>(x, w);

    attn_kernel<<<dim3(Tv/128, Bv*Hv), 128>>>(out);
}

// round 13
// speedup vs baseline: 2.2031x; 1.1255x over previous
#include <cuda_runtime.h>
#include <cuda_fp16.h>
#include <cmath>
#include <cstdint>

#define Bv 4
#define Tv 2048
#define Cv 1024
#define Hv 16
#define Dv 64
#define GM (Bv*Tv)      // 8192
#define GK Cv           // 1024
#define GN (3*Cv)       // 3072
#define SSH 72          // halves stride: attn sQ/sK/sV rows
#define PSH 40          // halves stride: attn sP rows
#define AST 40          // halves stride: gemm A rows (32 k + pad)
#define BST 136         // halves stride: gemm B rows (128 n + pad)

// Statics: QKV fp16 (48 MiB) + fp16 X (16 MiB) + fp16 W (6 MiB) = 70 MiB.
// RULE (6/6 failures explained): NEVER pass a __device__ symbol as a
// host-side kernel argument — reference statics in device code only.
__device__ __align__(16) __half g_Q[Bv*Hv*Tv*Dv];
__device__ __align__(16) __half g_K[Bv*Hv*Tv*Dv];
__device__ __align__(16) __half g_V[Bv*Hv*Tv*Dv];
__device__ __align__(16) __half g_Xh[GM*GK];
__device__ __align__(16) __half g_Wh[GK*GN];

__device__ __forceinline__ void mma_f16(float* c, const uint32_t* a, uint32_t b0, uint32_t b1) {
    asm volatile(
        "mma.sync.aligned.m16n8k16.row.col.f32.f16.f16.f32 "
        "{%0,%1,%2,%3}, {%4,%5,%6,%7}, {%8,%9}, {%0,%1,%2,%3};\n"
        : "+f"(c[0]), "+f"(c[1]), "+f"(c[2]), "+f"(c[3])
        : "r"(a[0]), "r"(a[1]), "r"(a[2]), "r"(a[3]), "r"(b0), "r"(b1));
}

__device__ __forceinline__ uint32_t smem_u32(const void* p) {
    uint32_t a;
    asm("{ .reg .u64 t; cvta.to.shared.u64 t, %1; cvt.u32.u64 %0, t; }" : "=r"(a) : "l"(p));
    return a;
}
__device__ __forceinline__ void ldmx4(uint32_t* r, uint32_t addr) {
    asm volatile("ldmatrix.sync.aligned.m8n8.x4.shared.b16 {%0,%1,%2,%3}, [%4];"
        : "=r"(r[0]), "=r"(r[1]), "=r"(r[2]), "=r"(r[3]) : "r"(addr));
}
__device__ __forceinline__ void ldmx4t(uint32_t* r, uint32_t addr) {
    asm volatile("ldmatrix.sync.aligned.m8n8.x4.trans.shared.b16 {%0,%1,%2,%3}, [%4];"
        : "=r"(r[0]), "=r"(r[1]), "=r"(r[2]), "=r"(r[3]) : "r"(addr));
}
__device__ __forceinline__ uint32_t h2pack(float a, float b) {
    __half2 h = __floats2half2_rn(a, b);
    return *(uint32_t*)&h;
}

// ---------------------------------------------------------------------------
// Prepasses: fp32 -> fp16.  Destination statics referenced in DEVICE code.
// ---------------------------------------------------------------------------
__global__ __launch_bounds__(256) void prep_x_half(const float4* __restrict__ src) {
    int i = blockIdx.x * blockDim.x + threadIdx.x;
    if (i < GM*GK/4) {
        float4 v = src[i];
        uint2 o;
        o.x = h2pack(v.x, v.y);
        o.y = h2pack(v.z, v.w);
        ((uint2*)g_Xh)[i] = o;
    }
}
__global__ __launch_bounds__(256) void prep_w_half(const float4* __restrict__ src) {
    int i = blockIdx.x * blockDim.x + threadIdx.x;
    if (i < GK*GN/4) {
        float4 v = src[i];
        uint2 o;
        o.x = h2pack(v.x, v.y);
        o.y = h2pack(v.z, v.w);
        ((uint2*)g_Wh)[i] = o;
    }
}

// ---------------------------------------------------------------------------
// Kernel 1: QKV projection GEMM — fp16 operands / fp32 accumulate.
// Block tile 128x128, k-tile 32, 512 threads = 16 warps (4m x 4n),
// warp tile 32x32.  Double-buffered smem, one sync per k-tile, plain
// fp16 global loads (prefetched in regs), ldmatrix fragments, m16n8k16.
// ---------------------------------------------------------------------------
__global__ __launch_bounds__(512) void qkv_gemm_kernel() {
    __shared__ __half sA[2][128][AST];   // [m][k]
    __shared__ __half sB[2][32][BST];    // [k][n]

    const int tid  = threadIdx.x;
    const int lane = tid & 31;
    const int wid  = tid >> 5;
    const int wm   = wid & 3;            // warp m index 0..3
    const int wn   = wid >> 2;           // warp n index 0..3
    const int m0   = blockIdx.y * 128;
    const int n0   = blockIdx.x * 128;

    const int l7  = lane & 7;
    const int lb3 = (lane >> 3) & 1;
    const int lb4 = (lane >> 4) & 1;

    // staging decomposition (halves): one uint4 (8 halves) per tensor per thread
    const int arow  = tid >> 2;            // 0..127
    const int acolh = (tid & 3) * 8;       // 0,8,16,24
    const int brow  = tid >> 4;            // 0..31
    const int bcolh = (tid & 15) * 8;      // 0..120

    const __half* Abase = g_Xh + (size_t)(m0 + arow) * GK + acolh;
    const __half* Bbase = g_Wh + (size_t)brow * GN + n0 + bcolh;

    const uint32_t bA = smem_u32(sA);
    const uint32_t bB = smem_u32(sB);

    uint4 ra = *(const uint4*)(Abase);
    uint4 rb = *(const uint4*)(Bbase);

    float acc[2][4][4];
    #pragma unroll
    for (int i = 0; i < 2; i++)
        #pragma unroll
        for (int j = 0; j < 4; j++)
            #pragma unroll
            for (int k = 0; k < 4; k++) acc[i][j][k] = 0.f;

    #pragma unroll 1
    for (int kt = 0; kt < GK/32; kt++) {
        const int pb = kt & 1;
        *(uint4*)(&sA[pb][arow][acolh]) = ra;
        *(uint4*)(&sB[pb][brow][bcolh]) = rb;
        __syncthreads();

        // prefetch next k-tile (plain loads; 16 warps hide the latency)
        if (kt < GK/32 - 1) {
            ra = *(const uint4*)(Abase + (size_t)(kt+1)*32);
            rb = *(const uint4*)(Bbase + (size_t)(kt+1)*32 * GN);
        }

        #pragma unroll
        for (int ks = 0; ks < 2; ks++) {
            const int kk = ks * 16;
            uint32_t af[2][4];
            #pragma unroll
            for (int mf = 0; mf < 2; mf++) {
                int row = wm*32 + mf*16 + l7 + 8*lb3;
                int col = kk + 8*lb4;
                ldmx4(af[mf], bA + (uint32_t)(pb*128*AST + row*AST + col)*2);
            }
            uint32_t bf[2][4];
            #pragma unroll
            for (int g = 0; g < 2; g++) {        // n groups of 16
                int row = kk + l7 + 8*lb3;       // k
                int col = wn*32 + g*16 + 8*lb4;  // n
                ldmx4t(bf[g], bB + (uint32_t)(pb*32*BST + row*BST + col)*2);
            }
            #pragma unroll
            for (int mf = 0; mf < 2; mf++)
                #pragma unroll
                for (int nf = 0; nf < 4; nf++)
                    mma_f16(acc[mf][nf], af[mf], bf[nf>>1][(nf&1)*2], bf[nf>>1][(nf&1)*2+1]);
        }
    }

    // Epilogue: fp16-round + scatter to Q/K/V in [B,H,T,D]
    #pragma unroll
    for (int mf = 0; mf < 2; mf++) {
        #pragma unroll
        for (int rr = 0; rr < 2; rr++) {
            int m  = m0 + wm*32 + mf*16 + (lane >> 2) + rr*8;
            int bb = m >> 11;
            int tt = m & (Tv - 1);
            #pragma unroll
            for (int nf = 0; nf < 4; nf++) {
                int n  = n0 + wn*32 + nf*8 + ((lane & 3) << 1);
                int s  = n >> 10;
                int cc = n & (Cv - 1);
                int h  = cc >> 6;
                int d  = cc & 63;
                __half* dst = (s == 0) ? g_Q : ((s == 1) ? g_K : g_V);
                size_t off = (((size_t)(bb*Hv + h))*Tv + tt)*Dv + d;
                __half2 hv = __floats2half2_rn(acc[mf][nf][rr*2+0], acc[mf][nf][rr*2+1]);
                *(__half2*)(dst + off) = hv;
            }
        }
    }
}

// ---------------------------------------------------------------------------
// Kernel 2: causal flash attention (unchanged from R10: fp16 operands /
// fp32 accumulate, 128 q/CTA, 32 q/warp, 64-key staging, 32-key S
// sub-chunks, ldmatrix).
// ---------------------------------------------------------------------------
__global__ __launch_bounds__(128) void attn_kernel(float* __restrict__ out) {
    __shared__ __half sQ[128*SSH];
    __shared__ __half sK[64*SSH];
    __shared__ __half sV[64*SSH];
    __shared__ __half sP[128*PSH];

    const int tid  = threadIdx.x;
    const int lane = tid & 31;
    const int wid  = tid >> 5;
    const int bh   = blockIdx.y;
    const int qt   = (Tv/128 - 1) - blockIdx.x;           // heavy tiles first
    const float scale = 0.125f;

    const __half* Qg = g_Q + (size_t)bh * Tv * Dv;
    const __half* Kg = g_K + (size_t)bh * Tv * Dv;
    const __half* Vg = g_V + (size_t)bh * Tv * Dv;

    const uint32_t bQ = smem_u32(sQ);
    const uint32_t bK = smem_u32(sK);
    const uint32_t bV = smem_u32(sV);
    const uint32_t bP = smem_u32(sP);

    const int l7  = lane & 7;
    const int lb3 = (lane >> 3) & 1;
    const int lb4 = (lane >> 4) & 1;

    {
        const uint4* src = (const uint4*)(Qg + (size_t)(qt*128 + tid)*Dv);
        uint4* dst = (uint4*)(sQ + tid*SSH);
        #pragma unroll
        for (int i = 0; i < 8; i++) dst[i] = src[i];
    }

    float o[2][8][4];
    #pragma unroll
    for (int mf = 0; mf < 2; mf++)
        #pragma unroll
        for (int i = 0; i < 8; i++)
            #pragma unroll
            for (int k = 0; k < 4; k++) o[mf][i][k] = 0.f;
    float mrow[2][2] = {{-INFINITY, -INFINITY}, {-INFINITY, -INFINITY}};
    float lrow[2][2] = {{0.f, 0.f}, {0.f, 0.f}};

    const int jmax = 2*qt + 1;
    #pragma unroll 1
    for (int j = 0; j <= jmax; j++) {
        __syncthreads();
        {
            int r  = tid >> 1;
            int c0 = (tid & 1) * 32;
            const uint4* ks = (const uint4*)(Kg + (size_t)(j*64 + r)*Dv + c0);
            const uint4* vs = (const uint4*)(Vg + (size_t)(j*64 + r)*Dv + c0);
            uint4* kd = (uint4*)(sK + r*SSH + c0);
            uint4* vd = (uint4*)(sV + r*SSH + c0);
            #pragma unroll
            for (int i = 0; i < 4; i++) { kd[i] = ks[i]; vd[i] = vs[i]; }
        }
        __syncthreads();

        const bool maybe_mask = (j >= 2*qt);

        #pragma unroll 1
        for (int sub = 0; sub < 2; sub++) {
            float s[2][4][4];
            #pragma unroll
            for (int mf = 0; mf < 2; mf++)
                #pragma unroll
                for (int i = 0; i < 4; i++)
                    #pragma unroll
                    for (int k = 0; k < 4; k++) s[mf][i][k] = 0.f;

            #pragma unroll
            for (int kt = 0; kt < 4; kt++) {
                const int kc = kt*16;
                uint32_t kb[2][4];
                #pragma unroll
                for (int g = 0; g < 2; g++) {
                    int row = sub*32 + g*16 + l7 + 8*lb4;
                    int col = kc + 8*lb3;
                    ldmx4(kb[g], bK + (uint32_t)(row*SSH + col)*2);
                }
                #pragma unroll
                for (int mf = 0; mf < 2; mf++) {
                    uint32_t qa[4];
                    int row = wid*32 + mf*16 + l7 + 8*lb3;
                    int col = kc + 8*lb4;
                    ldmx4(qa, bQ + (uint32_t)(row*SSH + col)*2);
                    #pragma unroll
                    for (int nf = 0; nf < 4; nf++)
                        mma_f16(s[mf][nf], qa, kb[nf>>1][(nf&1)*2], kb[nf>>1][(nf&1)*2+1]);
                }
            }

            #pragma unroll
            for (int mf = 0; mf < 2; mf++) {
                float mnew[2], alpha[2];
                #pragma unroll
                for (int rr = 0; rr < 2; rr++) {
                    int qrow = qt*128 + wid*32 + mf*16 + (lane >> 2) + rr*8;
                    float mx = -INFINITY;
                    #pragma unroll
                    for (int nf = 0; nf < 4; nf++) {
                        #pragma unroll
                        for (int cc = 0; cc < 2; cc++) {
                            float v = s[mf][nf][rr*2+cc] * scale;
                            if (maybe_mask) {
                                int kcol = j*64 + sub*32 + nf*8 + ((lane & 3) << 1) + cc;
                                if (kcol > qrow) v = -INFINITY;
                            }
                            s[mf][nf][rr*2+cc] = v;
                            mx = fmaxf(mx, v);
                        }
                    }
                    mx = fmaxf(mx, __shfl_xor_sync(0xffffffffu, mx, 1));
                    mx = fmaxf(mx, __shfl_xor_sync(0xffffffffu, mx, 2));
                    float mn = fmaxf(mrow[mf][rr], mx);
                    mnew[rr]  = mn;
                    alpha[rr] = __expf(mrow[mf][rr] - mn);
                    mrow[mf][rr] = mn;
                }
                float rs[2] = {0.f, 0.f};
                #pragma unroll
                for (int nf = 0; nf < 4; nf++) {
                    #pragma unroll
                    for (int rr = 0; rr < 2; rr++) {
                        #pragma unroll
                        for (int cc = 0; cc < 2; cc++) {
                            float p = __expf(s[mf][nf][rr*2+cc] - mnew[rr]);
                            s[mf][nf][rr*2+cc] = p;
                            rs[rr] += p;
                        }
                    }
                }
                #pragma unroll
                for (int rr = 0; rr < 2; rr++) {
                    float r2 = rs[rr];
                    r2 += __shfl_xor_sync(0xffffffffu, r2, 1);
                    r2 += __shfl_xor_sync(0xffffffffu, r2, 2);
                    lrow[mf][rr] = lrow[mf][rr]*alpha[rr] + r2;
                    #pragma unroll
                    for (int nf = 0; nf < 8; nf++) {
                        o[mf][nf][rr*2+0] *= alpha[rr];
                        o[mf][nf][rr*2+1] *= alpha[rr];
                    }
                }
                #pragma unroll
                for (int rr = 0; rr < 2; rr++) {
                    int r = wid*32 + mf*16 + (lane >> 2) + rr*8;
                    #pragma unroll
                    for (int nf = 0; nf < 4; nf++) {
                        __half2 h2 = __floats2half2_rn(s[mf][nf][rr*2+0], s[mf][nf][rr*2+1]);
                        *(__half2*)(sP + r*PSH + nf*8 + ((lane & 3) << 1)) = h2;
                    }
                }
            }
            __syncwarp();

            #pragma unroll
            for (int kt = 0; kt < 2; kt++) {
                const int kc = kt*16;
                uint32_t vb[4][4];
                #pragma unroll
                for (int g = 0; g < 4; g++) {
                    int row = sub*32 + kc + l7 + 8*lb3;
                    int col = g*16 + 8*lb4;
                    ldmx4t(vb[g], bV + (uint32_t)(row*SSH + col)*2);
                }
                #pragma unroll
                for (int mf = 0; mf < 2; mf++) {
                    uint32_t pa[4];
                    int row = wid*32 + mf*16 + l7 + 8*lb3;
                    int col = kc + 8*lb4;
                    ldmx4(pa, bP + (uint32_t)(row*PSH + col)*2);
                    #pragma unroll
                    for (int nb = 0; nb < 8; nb++)
                        mma_f16(o[mf][nb], pa, vb[nb>>1][(nb&1)*2], vb[nb>>1][(nb&1)*2+1]);
                }
            }
        }
    }

    const int b = bh >> 4;
    const int h = bh & 15;
    #pragma unroll
    for (int mf = 0; mf < 2; mf++) {
        #pragma unroll
        for (int rr = 0; rr < 2; rr++) {
            float inv = 1.0f / lrow[mf][rr];
            int q = qt*128 + wid*32 + mf*16 + (lane >> 2) + rr*8;
            float* dst = out + ((size_t)b*Tv + q)*Cv + h*Dv;
            #pragma unroll
            for (int nf = 0; nf < 8; nf++) {
                int dd = nf*8 + ((lane & 3) << 1);
                float2 v2;
                v2.x = o[mf][nf][rr*2+0] * inv;
                v2.y = o[mf][nf][rr*2+1] * inv;
                *(float2*)(dst + dd) = v2;
            }
        }
    }
}

extern "C" void kernel_launch(void* const* d_in, const int* in_sizes, int n_in,
                              void* d_out, int out_size) {
    const float* x = (const float*)d_in[0];     // [B,T,C] fp32
    const float* w = (const float*)d_in[1];     // [C,3C] fp32
    float* out = (float*)d_out;                 // [B,T,C] fp32

    prep_x_half<<<(GM*GK/4 + 255)/256, 256>>>((const float4*)x);
    prep_w_half<<<(GK*GN/4 + 255)/256, 256>>>((const float4*)w);

    qkv_gemm_kernel<<<dim3(GN/128, GM/128), 512>>>();

    attn_kernel<<<dim3(Tv/128, Bv*Hv), 128>>>(out);
}

// round 15
// speedup vs baseline: 2.2551x; 1.0236x over previous
#include <cuda_runtime.h>
#include <cuda_fp16.h>
#include <cmath>
#include <cstdint>

#define Bv 4
#define Tv 2048
#define Cv 1024
#define Hv 16
#define Dv 64
#define GM (Bv*Tv)      // 8192
#define GK Cv           // 1024
#define GN (3*Cv)       // 3072
#define SSH 72          // halves stride: attn sQ/sK/sV rows
#define PSH 40          // halves stride: attn sP rows
#define AST 40          // halves stride: gemm A rows (32 k + pad; 80B = 16B-aligned)
#define BST 264         // halves stride: gemm B rows (256 n + pad; 528B = 16B-aligned)
#define ABUF (128*AST)  // 5120 halves per A buffer
#define BBUF (32*BST)   // 8448 halves per B buffer

// Statics: QKV fp16 (48 MiB) + fp16 X (16 MiB) + fp16 W (6 MiB) = 70 MiB.
// RULE: never pass a __device__ symbol as a host-side kernel argument.
__device__ __align__(16) __half g_Q[Bv*Hv*Tv*Dv];
__device__ __align__(16) __half g_K[Bv*Hv*Tv*Dv];
__device__ __align__(16) __half g_V[Bv*Hv*Tv*Dv];
__device__ __align__(16) __half g_Xh[GM*GK];
__device__ __align__(16) __half g_Wh[GK*GN];

__device__ __forceinline__ void mma_f16(float* c, const uint32_t* a, uint32_t b0, uint32_t b1) {
    asm volatile(
        "mma.sync.aligned.m16n8k16.row.col.f32.f16.f16.f32 "
        "{%0,%1,%2,%3}, {%4,%5,%6,%7}, {%8,%9}, {%0,%1,%2,%3};\n"
        : "+f"(c[0]), "+f"(c[1]), "+f"(c[2]), "+f"(c[3])
        : "r"(a[0]), "r"(a[1]), "r"(a[2]), "r"(a[3]), "r"(b0), "r"(b1));
}

__device__ __forceinline__ uint32_t smem_u32(const void* p) {
    uint32_t a;
    asm("{ .reg .u64 t; cvta.to.shared.u64 t, %1; cvt.u32.u64 %0, t; }" : "=r"(a) : "l"(p));
    return a;
}
__device__ __forceinline__ void ldmx4(uint32_t* r, uint32_t addr) {
    asm volatile("ldmatrix.sync.aligned.m8n8.x4.shared.b16 {%0,%1,%2,%3}, [%4];"
        : "=r"(r[0]), "=r"(r[1]), "=r"(r[2]), "=r"(r[3]) : "r"(addr));
}
__device__ __forceinline__ void ldmx4t(uint32_t* r, uint32_t addr) {
    asm volatile("ldmatrix.sync.aligned.m8n8.x4.trans.shared.b16 {%0,%1,%2,%3}, [%4];"
        : "=r"(r[0]), "=r"(r[1]), "=r"(r[2]), "=r"(r[3]) : "r"(addr));
}
__device__ __forceinline__ uint32_t h2pack(float a, float b) {
    __half2 h = __floats2half2_rn(a, b);
    return *(uint32_t*)&h;
}

// ---------------------------------------------------------------------------
// Prepasses: fp32 -> fp16.  Destination statics referenced in DEVICE code.
// ---------------------------------------------------------------------------
__global__ __launch_bounds__(256) void prep_x_half(const float4* __restrict__ src) {
    int i = blockIdx.x * blockDim.x + threadIdx.x;
    if (i < GM*GK/4) {
        float4 v = src[i];
        uint2 o;
        o.x = h2pack(v.x, v.y);
        o.y = h2pack(v.z, v.w);
        ((uint2*)g_Xh)[i] = o;
    }
}
__global__ __launch_bounds__(256) void prep_w_half(const float4* __restrict__ src) {
    int i = blockIdx.x * blockDim.x + threadIdx.x;
    if (i < GK*GN/4) {
        float4 v = src[i];
        uint2 o;
        o.x = h2pack(v.x, v.y);
        o.y = h2pack(v.z, v.w);
        ((uint2*)g_Wh)[i] = o;
    }
}

// ---------------------------------------------------------------------------
// Kernel 1: QKV projection GEMM — fp16 operands / fp32 accumulate.
// Block tile 128x256, k-tile 32, 512 threads = 16 warps (4m x 4n),
// warp tile 32x64.  Double-buffered dynamic smem, one sync per k-tile,
// plain fp16 global loads (prefetched in regs), ldmatrix, m16n8k16.
// ---------------------------------------------------------------------------
__global__ __launch_bounds__(512) void qkv_gemm_kernel() {
    extern __shared__ __half dsm[];      // [A0 A1 | B0 B1]

    const int tid  = threadIdx.x;
    const int lane = tid & 31;
    const int wid  = tid >> 5;
    const int wm   = wid & 3;            // warp m index 0..3
    const int wn   = wid >> 2;           // warp n index 0..3
    const int m0   = blockIdx.y * 128;
    const int n0   = blockIdx.x * 256;

    const int l7  = lane & 7;
    const int lb3 = (lane >> 3) & 1;
    const int lb4 = (lane >> 4) & 1;

    // staging decomposition (halves)
    const int arow  = tid >> 2;            // 0..127, one uint4 per thread
    const int acolh = (tid & 3) * 8;       // 0,8,16,24
    const int brow  = tid & 31;            // 0..31, two uint4 per thread
    const int bcolh = (tid >> 5) * 16;     // 0..240

    const __half* Abase = g_Xh + (size_t)(m0 + arow) * GK + acolh;
    const __half* Bbase = g_Wh + (size_t)brow * GN + n0 + bcolh;

    const uint32_t bS = smem_u32(dsm);

    uint4 ra  = *(const uint4*)(Abase);
    uint4 rb0 = *(const uint4*)(Bbase);
    uint4 rb1 = *(const uint4*)(Bbase + 8);

    float acc[2][8][4];
    #pragma unroll
    for (int i = 0; i < 2; i++)
        #pragma unroll
        for (int j = 0; j < 8; j++)
            #pragma unroll
            for (int k = 0; k < 4; k++) acc[i][j][k] = 0.f;

    #pragma unroll 1
    for (int kt = 0; kt < GK/32; kt++) {
        const int pb = kt & 1;
        const uint32_t aOff = (uint32_t)pb * ABUF;              // halves
        const uint32_t bOff = 2u*ABUF + (uint32_t)pb * BBUF;    // halves
        *(uint4*)(dsm + aOff + arow*AST + acolh) = ra;
        *(uint4*)(dsm + bOff + brow*BST + bcolh)     = rb0;
        *(uint4*)(dsm + bOff + brow*BST + bcolh + 8) = rb1;
        __syncthreads();

        // prefetch next k-tile
        if (kt < GK/32 - 1) {
            ra  = *(const uint4*)(Abase + (size_t)(kt+1)*32);
            rb0 = *(const uint4*)(Bbase + (size_t)(kt+1)*32 * GN);
            rb1 = *(const uint4*)(Bbase + (size_t)(kt+1)*32 * GN + 8);
        }

        #pragma unroll
        for (int ks = 0; ks < 2; ks++) {
            const int kk = ks * 16;
            uint32_t af[2][4];
            #pragma unroll
            for (int mf = 0; mf < 2; mf++) {
                int row = wm*32 + mf*16 + l7 + 8*lb3;
                int col = kk + 8*lb4;
                ldmx4(af[mf], bS + (aOff + (uint32_t)(row*AST + col))*2);
            }
            uint32_t bf[4][4];
            #pragma unroll
            for (int g = 0; g < 4; g++) {        // n groups of 16
                int row = kk + l7 + 8*lb3;       // k
                int col = wn*64 + g*16 + 8*lb4;  // n
                ldmx4t(bf[g], bS + (bOff + (uint32_t)(row*BST + col))*2);
            }
            #pragma unroll
            for (int mf = 0; mf < 2; mf++)
                #pragma unroll
                for (int nf = 0; nf < 8; nf++)
                    mma_f16(acc[mf][nf], af[mf], bf[nf>>1][(nf&1)*2], bf[nf>>1][(nf&1)*2+1]);
        }
    }

    // Epilogue: fp16-round + scatter to Q/K/V in [B,H,T,D]
    #pragma unroll
    for (int mf = 0; mf < 2; mf++) {
        #pragma unroll
        for (int rr = 0; rr < 2; rr++) {
            int m  = m0 + wm*32 + mf*16 + (lane >> 2) + rr*8;
            int bb = m >> 11;
            int tt = m & (Tv - 1);
            #pragma unroll
            for (int nf = 0; nf < 8; nf++) {
                int n  = n0 + wn*64 + nf*8 + ((lane & 3) << 1);
                int s  = n >> 10;
                int cc = n & (Cv - 1);
                int h  = cc >> 6;
                int d  = cc & 63;
                __half* dst = (s == 0) ? g_Q : ((s == 1) ? g_K : g_V);
                size_t off = (((size_t)(bb*Hv + h))*Tv + tt)*Dv + d;
                __half2 hv = __floats2half2_rn(acc[mf][nf][rr*2+0], acc[mf][nf][rr*2+1]);
                *(__half2*)(dst + off) = hv;
            }
        }
    }
}

// ---------------------------------------------------------------------------
// Kernel 2: causal flash attention (R10 structure; launch_bounds(128,4) to
// fit a 4th CTA per SM — regs capped at 128).
// ---------------------------------------------------------------------------
__global__ __launch_bounds__(128, 4) void attn_kernel(float* __restrict__ out) {
    __shared__ __half sQ[128*SSH];
    __shared__ __half sK[64*SSH];
    __shared__ __half sV[64*SSH];
    __shared__ __half sP[128*PSH];

    const int tid  = threadIdx.x;
    const int lane = tid & 31;
    const int wid  = tid >> 5;
    const int bh   = blockIdx.y;
    const int qt   = (Tv/128 - 1) - blockIdx.x;           // heavy tiles first
    const float scale = 0.125f;

    const __half* Qg = g_Q + (size_t)bh * Tv * Dv;
    const __half* Kg = g_K + (size_t)bh * Tv * Dv;
    const __half* Vg = g_V + (size_t)bh * Tv * Dv;

    const uint32_t bQ = smem_u32(sQ);
    const uint32_t bK = smem_u32(sK);
    const uint32_t bV = smem_u32(sV);
    const uint32_t bP = smem_u32(sP);

    const int l7  = lane & 7;
    const int lb3 = (lane >> 3) & 1;
    const int lb4 = (lane >> 4) & 1;

    {
        const uint4* src = (const uint4*)(Qg + (size_t)(qt*128 + tid)*Dv);
        uint4* dst = (uint4*)(sQ + tid*SSH);
        #pragma unroll
        for (int i = 0; i < 8; i++) dst[i] = src[i];
    }

    float o[2][8][4];
    #pragma unroll
    for (int mf = 0; mf < 2; mf++)
        #pragma unroll
        for (int i = 0; i < 8; i++)
            #pragma unroll
            for (int k = 0; k < 4; k++) o[mf][i][k] = 0.f;
    float mrow[2][2] = {{-INFINITY, -INFINITY}, {-INFINITY, -INFINITY}};
    float lrow[2][2] = {{0.f, 0.f}, {0.f, 0.f}};

    const int jmax = 2*qt + 1;
    #pragma unroll 1
    for (int j = 0; j <= jmax; j++) {
        __syncthreads();
        {
            int r  = tid >> 1;
            int c0 = (tid & 1) * 32;
            const uint4* ks = (const uint4*)(Kg + (size_t)(j*64 + r)*Dv + c0);
            const uint4* vs = (const uint4*)(Vg + (size_t)(j*64 + r)*Dv + c0);
            uint4* kd = (uint4*)(sK + r*SSH + c0);
            uint4* vd = (uint4*)(sV + r*SSH + c0);
            #pragma unroll
            for (int i = 0; i < 4; i++) { kd[i] = ks[i]; vd[i] = vs[i]; }
        }
        __syncthreads();

        const bool maybe_mask = (j >= 2*qt);

        #pragma unroll 1
        for (int sub = 0; sub < 2; sub++) {
            float s[2][4][4];
            #pragma unroll
            for (int mf = 0; mf < 2; mf++)
                #pragma unroll
                for (int i = 0; i < 4; i++)
                    #pragma unroll
                    for (int k = 0; k < 4; k++) s[mf][i][k] = 0.f;

            #pragma unroll
            for (int kt = 0; kt < 4; kt++) {
                const int kc = kt*16;
                uint32_t kb[2][4];
                #pragma unroll
                for (int g = 0; g < 2; g++) {
                    int row = sub*32 + g*16 + l7 + 8*lb4;
                    int col = kc + 8*lb3;
                    ldmx4(kb[g], bK + (uint32_t)(row*SSH + col)*2);
                }
                #pragma unroll
                for (int mf = 0; mf < 2; mf++) {
                    uint32_t qa[4];
                    int row = wid*32 + mf*16 + l7 + 8*lb3;
                    int col = kc + 8*lb4;
                    ldmx4(qa, bQ + (uint32_t)(row*SSH + col)*2);
                    #pragma unroll
                    for (int nf = 0; nf < 4; nf++)
                        mma_f16(s[mf][nf], qa, kb[nf>>1][(nf&1)*2], kb[nf>>1][(nf&1)*2+1]);
                }
            }

            #pragma unroll
            for (int mf = 0; mf < 2; mf++) {
                float mnew[2], alpha[2];
                #pragma unroll
                for (int rr = 0; rr < 2; rr++) {
                    int qrow = qt*128 + wid*32 + mf*16 + (lane >> 2) + rr*8;
                    float mx = -INFINITY;
                    #pragma unroll
                    for (int nf = 0; nf < 4; nf++) {
                        #pragma unroll
                        for (int cc = 0; cc < 2; cc++) {
                            float v = s[mf][nf][rr*2+cc] * scale;
                            if (maybe_mask) {
                                int kcol = j*64 + sub*32 + nf*8 + ((lane & 3) << 1) + cc;
                                if (kcol > qrow) v = -INFINITY;
                            }
                            s[mf][nf][rr*2+cc] = v;
                            mx = fmaxf(mx, v);
                        }
                    }
                    mx = fmaxf(mx, __shfl_xor_sync(0xffffffffu, mx, 1));
                    mx = fmaxf(mx, __shfl_xor_sync(0xffffffffu, mx, 2));
                    float mn = fmaxf(mrow[mf][rr], mx);
                    mnew[rr]  = mn;
                    alpha[rr] = __expf(mrow[mf][rr] - mn);
                    mrow[mf][rr] = mn;
                }
                float rs[2] = {0.f, 0.f};
                #pragma unroll
                for (int nf = 0; nf < 4; nf++) {
                    #pragma unroll
                    for (int rr = 0; rr < 2; rr++) {
                        #pragma unroll
                        for (int cc = 0; cc < 2; cc++) {
                            float p = __expf(s[mf][nf][rr*2+cc] - mnew[rr]);
                            s[mf][nf][rr*2+cc] = p;
                            rs[rr] += p;
                        }
                    }
                }
                #pragma unroll
                for (int rr = 0; rr < 2; rr++) {
                    float r2 = rs[rr];
                    r2 += __shfl_xor_sync(0xffffffffu, r2, 1);
                    r2 += __shfl_xor_sync(0xffffffffu, r2, 2);
                    lrow[mf][rr] = lrow[mf][rr]*alpha[rr] + r2;
                    #pragma unroll
                    for (int nf = 0; nf < 8; nf++) {
                        o[mf][nf][rr*2+0] *= alpha[rr];
                        o[mf][nf][rr*2+1] *= alpha[rr];
                    }
                }
                #pragma unroll
                for (int rr = 0; rr < 2; rr++) {
                    int r = wid*32 + mf*16 + (lane >> 2) + rr*8;
                    #pragma unroll
                    for (int nf = 0; nf < 4; nf++) {
                        __half2 h2 = __floats2half2_rn(s[mf][nf][rr*2+0], s[mf][nf][rr*2+1]);
                        *(__half2*)(sP + r*PSH + nf*8 + ((lane & 3) << 1)) = h2;
                    }
                }
            }
            __syncwarp();

            #pragma unroll
            for (int kt = 0; kt < 2; kt++) {
                const int kc = kt*16;
                uint32_t vb[4][4];
                #pragma unroll
                for (int g = 0; g < 4; g++) {
                    int row = sub*32 + kc + l7 + 8*lb3;
                    int col = g*16 + 8*lb4;
                    ldmx4t(vb[g], bV + (uint32_t)(row*SSH + col)*2);
                }
                #pragma unroll
                for (int mf = 0; mf < 2; mf++) {
                    uint32_t pa[4];
                    int row = wid*32 + mf*16 + l7 + 8*lb3;
                    int col = kc + 8*lb4;
                    ldmx4(pa, bP + (uint32_t)(row*PSH + col)*2);
                    #pragma unroll
                    for (int nb = 0; nb < 8; nb++)
                        mma_f16(o[mf][nb], pa, vb[nb>>1][(nb&1)*2], vb[nb>>1][(nb&1)*2+1]);
                }
            }
        }
    }

    const int b = bh >> 4;
    const int h = bh & 15;
    #pragma unroll
    for (int mf = 0; mf < 2; mf++) {
        #pragma unroll
        for (int rr = 0; rr < 2; rr++) {
            float inv = 1.0f / lrow[mf][rr];
            int q = qt*128 + wid*32 + mf*16 + (lane >> 2) + rr*8;
            float* dst = out + ((size_t)b*Tv + q)*Cv + h*Dv;
            #pragma unroll
            for (int nf = 0; nf < 8; nf++) {
                int dd = nf*8 + ((lane & 3) << 1);
                float2 v2;
                v2.x = o[mf][nf][rr*2+0] * inv;
                v2.y = o[mf][nf][rr*2+1] * inv;
                *(float2*)(dst + dd) = v2;
            }
        }
    }
}

extern "C" void kernel_launch(void* const* d_in, const int* in_sizes, int n_in,
                              void* d_out, int out_size) {
    const float* x = (const float*)d_in[0];     // [B,T,C] fp32
    const float* w = (const float*)d_in[1];     // [C,3C] fp32
    float* out = (float*)d_out;                 // [B,T,C] fp32

    prep_x_half<<<(GM*GK/4 + 255)/256, 256>>>((const float4*)x);
    prep_w_half<<<(GK*GN/4 + 255)/256, 256>>>((const float4*)w);

    const int gsmem = (2*ABUF + 2*BBUF) * 2;     // 54272 B
    cudaFuncSetAttribute(qkv_gemm_kernel, cudaFuncAttributeMaxDynamicSharedMemorySize, gsmem);
    qkv_gemm_kernel<<<dim3(GN/256, GM/128), 512, gsmem>>>();

    attn_kernel<<<dim3(Tv/128, Bv*Hv), 128>>>(out);
}

// round 16
// speedup vs baseline: 2.3058x; 1.0225x over previous
#include <cuda_runtime.h>
#include <cuda_fp16.h>
#include <cmath>
#include <cstdint>

#define Bv 4
#define Tv 2048
#define Cv 1024
#define Hv 16
#define Dv 64
#define GM (Bv*Tv)      // 8192
#define GK Cv           // 1024
#define GN (3*Cv)       // 3072
#define SSH 72          // halves stride: attn sQ/sK/sV rows
#define PSH 40          // halves stride: attn sP rows
#define AST 72          // halves stride: gemm A rows (64 k + pad; 144B 16B-aligned)
#define BST 264         // halves stride: gemm B rows (256 n + pad; 528B 16B-aligned)
#define ABUF (128*AST)  // 9216 halves per A buffer
#define BBUF (64*BST)   // 16896 halves per B buffer

// Statics: QKV fp16 (48 MiB) + fp16 X (16 MiB) + fp16 W (6 MiB) = 70 MiB.
// RULE: never pass a __device__ symbol as a host-side kernel argument.
__device__ __align__(16) __half g_Q[Bv*Hv*Tv*Dv];
__device__ __align__(16) __half g_K[Bv*Hv*Tv*Dv];
__device__ __align__(16) __half g_V[Bv*Hv*Tv*Dv];
__device__ __align__(16) __half g_Xh[GM*GK];
__device__ __align__(16) __half g_Wh[GK*GN];

__device__ __forceinline__ void mma_f16(float* c, const uint32_t* a, uint32_t b0, uint32_t b1) {
    asm volatile(
        "mma.sync.aligned.m16n8k16.row.col.f32.f16.f16.f32 "
        "{%0,%1,%2,%3}, {%4,%5,%6,%7}, {%8,%9}, {%0,%1,%2,%3};\n"
        : "+f"(c[0]), "+f"(c[1]), "+f"(c[2]), "+f"(c[3])
        : "r"(a[0]), "r"(a[1]), "r"(a[2]), "r"(a[3]), "r"(b0), "r"(b1));
}

__device__ __forceinline__ uint32_t smem_u32(const void* p) {
    uint32_t a;
    asm("{ .reg .u64 t; cvta.to.shared.u64 t, %1; cvt.u32.u64 %0, t; }" : "=r"(a) : "l"(p));
    return a;
}
__device__ __forceinline__ void ldmx4(uint32_t* r, uint32_t addr) {
    asm volatile("ldmatrix.sync.aligned.m8n8.x4.shared.b16 {%0,%1,%2,%3}, [%4];"
        : "=r"(r[0]), "=r"(r[1]), "=r"(r[2]), "=r"(r[3]) : "r"(addr));
}
__device__ __forceinline__ void ldmx4t(uint32_t* r, uint32_t addr) {
    asm volatile("ldmatrix.sync.aligned.m8n8.x4.trans.shared.b16 {%0,%1,%2,%3}, [%4];"
        : "=r"(r[0]), "=r"(r[1]), "=r"(r[2]), "=r"(r[3]) : "r"(addr));
}
__device__ __forceinline__ uint32_t h2pack(float a, float b) {
    __half2 h = __floats2half2_rn(a, b);
    return *(uint32_t*)&h;
}

// ---------------------------------------------------------------------------
// Prepasses: fp32 -> fp16.  Destination statics referenced in DEVICE code.
// ---------------------------------------------------------------------------
__global__ __launch_bounds__(256) void prep_x_half(const float4* __restrict__ src) {
    int i = blockIdx.x * blockDim.x + threadIdx.x;
    if (i < GM*GK/4) {
        float4 v = src[i];
        uint2 o;
        o.x = h2pack(v.x, v.y);
        o.y = h2pack(v.z, v.w);
        ((uint2*)g_Xh)[i] = o;
    }
}
__global__ __launch_bounds__(256) void prep_w_half(const float4* __restrict__ src) {
    int i = blockIdx.x * blockDim.x + threadIdx.x;
    if (i < GK*GN/4) {
        float4 v = src[i];
        uint2 o;
        o.x = h2pack(v.x, v.y);
        o.y = h2pack(v.z, v.w);
        ((uint2*)g_Wh)[i] = o;
    }
}

// ---------------------------------------------------------------------------
// Kernel 1: QKV projection GEMM — fp16 operands / fp32 accumulate.
// Block tile 128x256, k-tile 64 (4 x k16), 512 threads = 16 warps (4m x 4n),
// warp tile 32x64.  Double-buffered dynamic smem (102 KB), ONE sync per
// 64-wide k-tile (16 syncs total), ldmatrix, m16n8k16.
// ---------------------------------------------------------------------------
__global__ __launch_bounds__(512) void qkv_gemm_kernel() {
    extern __shared__ __half dsm[];      // [A0 A1 | B0 B1]

    const int tid  = threadIdx.x;
    const int lane = tid & 31;
    const int wid  = tid >> 5;
    const int wm   = wid & 3;            // warp m index 0..3
    const int wn   = wid >> 2;           // warp n index 0..3
    const int m0   = blockIdx.y * 128;
    const int n0   = blockIdx.x * 256;

    const int l7  = lane & 7;
    const int lb3 = (lane >> 3) & 1;
    const int lb4 = (lane >> 4) & 1;

    // staging decomposition (halves)
    const int arow  = tid >> 2;            // 0..127, two uint4 per thread
    const int acolh = (tid & 3) * 16;      // 0,16,32,48
    const int brow  = tid >> 3;            // 0..63, four uint4 per thread
    const int bcolh = (tid & 7) * 32;      // 0..224

    const __half* Abase = g_Xh + (size_t)(m0 + arow) * GK + acolh;
    const __half* Bbase = g_Wh + (size_t)brow * GN + n0 + bcolh;

    const uint32_t bS = smem_u32(dsm);

    uint4 ra0 = *(const uint4*)(Abase);
    uint4 ra1 = *(const uint4*)(Abase + 8);
    uint4 rb0 = *(const uint4*)(Bbase);
    uint4 rb1 = *(const uint4*)(Bbase + 8);
    uint4 rb2 = *(const uint4*)(Bbase + 16);
    uint4 rb3 = *(const uint4*)(Bbase + 24);

    float acc[2][8][4];
    #pragma unroll
    for (int i = 0; i < 2; i++)
        #pragma unroll
        for (int j = 0; j < 8; j++)
            #pragma unroll
            for (int k = 0; k < 4; k++) acc[i][j][k] = 0.f;

    #pragma unroll 1
    for (int kt = 0; kt < GK/64; kt++) {
        const int pb = kt & 1;
        const uint32_t aOff = (uint32_t)pb * ABUF;              // halves
        const uint32_t bOff = 2u*ABUF + (uint32_t)pb * BBUF;    // halves
        *(uint4*)(dsm + aOff + arow*AST + acolh)      = ra0;
        *(uint4*)(dsm + aOff + arow*AST + acolh + 8)  = ra1;
        *(uint4*)(dsm + bOff + brow*BST + bcolh)      = rb0;
        *(uint4*)(dsm + bOff + brow*BST + bcolh + 8)  = rb1;
        *(uint4*)(dsm + bOff + brow*BST + bcolh + 16) = rb2;
        *(uint4*)(dsm + bOff + brow*BST + bcolh + 24) = rb3;
        __syncthreads();

        // prefetch next k-tile
        if (kt < GK/64 - 1) {
            const __half* an = Abase + (size_t)(kt+1)*64;
            const __half* bn = Bbase + (size_t)(kt+1)*64 * GN;
            ra0 = *(const uint4*)(an);
            ra1 = *(const uint4*)(an + 8);
            rb0 = *(const uint4*)(bn);
            rb1 = *(const uint4*)(bn + 8);
            rb2 = *(const uint4*)(bn + 16);
            rb3 = *(const uint4*)(bn + 24);
        }

        #pragma unroll
        for (int ks = 0; ks < 4; ks++) {
            const int kk = ks * 16;
            uint32_t af[2][4];
            #pragma unroll
            for (int mf = 0; mf < 2; mf++) {
                int row = wm*32 + mf*16 + l7 + 8*lb3;
                int col = kk + 8*lb4;
                ldmx4(af[mf], bS + (aOff + (uint32_t)(row*AST + col))*2);
            }
            uint32_t bf[4][4];
            #pragma unroll
            for (int g = 0; g < 4; g++) {        // n groups of 16
                int row = kk + l7 + 8*lb3;       // k
                int col = wn*64 + g*16 + 8*lb4;  // n
                ldmx4t(bf[g], bS + (bOff + (uint32_t)(row*BST + col))*2);
            }
            #pragma unroll
            for (int mf = 0; mf < 2; mf++)
                #pragma unroll
                for (int nf = 0; nf < 8; nf++)
                    mma_f16(acc[mf][nf], af[mf], bf[nf>>1][(nf&1)*2], bf[nf>>1][(nf&1)*2+1]);
        }
    }

    // Epilogue: fp16-round + scatter to Q/K/V in [B,H,T,D]
    #pragma unroll
    for (int mf = 0; mf < 2; mf++) {
        #pragma unroll
        for (int rr = 0; rr < 2; rr++) {
            int m  = m0 + wm*32 + mf*16 + (lane >> 2) + rr*8;
            int bb = m >> 11;
            int tt = m & (Tv - 1);
            #pragma unroll
            for (int nf = 0; nf < 8; nf++) {
                int n  = n0 + wn*64 + nf*8 + ((lane & 3) << 1);
                int s  = n >> 10;
                int cc = n & (Cv - 1);
                int h  = cc >> 6;
                int d  = cc & 63;
                __half* dst = (s == 0) ? g_Q : ((s == 1) ? g_K : g_V);
                size_t off = (((size_t)(bb*Hv + h))*Tv + tt)*Dv + d;
                __half2 hv = __floats2half2_rn(acc[mf][nf][rr*2+0], acc[mf][nf][rr*2+1]);
                *(__half2*)(dst + off) = hv;
            }
        }
    }
}

// ---------------------------------------------------------------------------
// Kernel 2: causal flash attention (unchanged from R15).
// ---------------------------------------------------------------------------
__global__ __launch_bounds__(128, 4) void attn_kernel(float* __restrict__ out) {
    __shared__ __half sQ[128*SSH];
    __shared__ __half sK[64*SSH];
    __shared__ __half sV[64*SSH];
    __shared__ __half sP[128*PSH];

    const int tid  = threadIdx.x;
    const int lane = tid & 31;
    const int wid  = tid >> 5;
    const int bh   = blockIdx.y;
    const int qt   = (Tv/128 - 1) - blockIdx.x;           // heavy tiles first
    const float scale = 0.125f;

    const __half* Qg = g_Q + (size_t)bh * Tv * Dv;
    const __half* Kg = g_K + (size_t)bh * Tv * Dv;
    const __half* Vg = g_V + (size_t)bh * Tv * Dv;

    const uint32_t bQ = smem_u32(sQ);
    const uint32_t bK = smem_u32(sK);
    const uint32_t bV = smem_u32(sV);
    const uint32_t bP = smem_u32(sP);

    const int l7  = lane & 7;
    const int lb3 = (lane >> 3) & 1;
    const int lb4 = (lane >> 4) & 1;

    {
        const uint4* src = (const uint4*)(Qg + (size_t)(qt*128 + tid)*Dv);
        uint4* dst = (uint4*)(sQ + tid*SSH);
        #pragma unroll
        for (int i = 0; i < 8; i++) dst[i] = src[i];
    }

    float o[2][8][4];
    #pragma unroll
    for (int mf = 0; mf < 2; mf++)
        #pragma unroll
        for (int i = 0; i < 8; i++)
            #pragma unroll
            for (int k = 0; k < 4; k++) o[mf][i][k] = 0.f;
    float mrow[2][2] = {{-INFINITY, -INFINITY}, {-INFINITY, -INFINITY}};
    float lrow[2][2] = {{0.f, 0.f}, {0.f, 0.f}};

    const int jmax = 2*qt + 1;
    #pragma unroll 1
    for (int j = 0; j <= jmax; j++) {
        __syncthreads();
        {
            int r  = tid >> 1;
            int c0 = (tid & 1) * 32;
            const uint4* ks = (const uint4*)(Kg + (size_t)(j*64 + r)*Dv + c0);
            const uint4* vs = (const uint4*)(Vg + (size_t)(j*64 + r)*Dv + c0);
            uint4* kd = (uint4*)(sK + r*SSH + c0);
            uint4* vd = (uint4*)(sV + r*SSH + c0);
            #pragma unroll
            for (int i = 0; i < 4; i++) { kd[i] = ks[i]; vd[i] = vs[i]; }
        }
        __syncthreads();

        const bool maybe_mask = (j >= 2*qt);

        #pragma unroll 1
        for (int sub = 0; sub < 2; sub++) {
            float s[2][4][4];
            #pragma unroll
            for (int mf = 0; mf < 2; mf++)
                #pragma unroll
                for (int i = 0; i < 4; i++)
                    #pragma unroll
                    for (int k = 0; k < 4; k++) s[mf][i][k] = 0.f;

            #pragma unroll
            for (int kt = 0; kt < 4; kt++) {
                const int kc = kt*16;
                uint32_t kb[2][4];
                #pragma unroll
                for (int g = 0; g < 2; g++) {
                    int row = sub*32 + g*16 + l7 + 8*lb4;
                    int col = kc + 8*lb3;
                    ldmx4(kb[g], bK + (uint32_t)(row*SSH + col)*2);
                }
                #pragma unroll
                for (int mf = 0; mf < 2; mf++) {
                    uint32_t qa[4];
                    int row = wid*32 + mf*16 + l7 + 8*lb3;
                    int col = kc + 8*lb4;
                    ldmx4(qa, bQ + (uint32_t)(row*SSH + col)*2);
                    #pragma unroll
                    for (int nf = 0; nf < 4; nf++)
                        mma_f16(s[mf][nf], qa, kb[nf>>1][(nf&1)*2], kb[nf>>1][(nf&1)*2+1]);
                }
            }

            #pragma unroll
            for (int mf = 0; mf < 2; mf++) {
                float mnew[2], alpha[2];
                #pragma unroll
                for (int rr = 0; rr < 2; rr++) {
                    int qrow = qt*128 + wid*32 + mf*16 + (lane >> 2) + rr*8;
                    float mx = -INFINITY;
                    #pragma unroll
                    for (int nf = 0; nf < 4; nf++) {
                        #pragma unroll
                        for (int cc = 0; cc < 2; cc++) {
                            float v = s[mf][nf][rr*2+cc] * scale;
                            if (maybe_mask) {
                                int kcol = j*64 + sub*32 + nf*8 + ((lane & 3) << 1) + cc;
                                if (kcol > qrow) v = -INFINITY;
                            }
                            s[mf][nf][rr*2+cc] = v;
                            mx = fmaxf(mx, v);
                        }
                    }
                    mx = fmaxf(mx, __shfl_xor_sync(0xffffffffu, mx, 1));
                    mx = fmaxf(mx, __shfl_xor_sync(0xffffffffu, mx, 2));
                    float mn = fmaxf(mrow[mf][rr], mx);
                    mnew[rr]  = mn;
                    alpha[rr] = __expf(mrow[mf][rr] - mn);
                    mrow[mf][rr] = mn;
                }
                float rs[2] = {0.f, 0.f};
                #pragma unroll
                for (int nf = 0; nf < 4; nf++) {
                    #pragma unroll
                    for (int rr = 0; rr < 2; rr++) {
                        #pragma unroll
                        for (int cc = 0; cc < 2; cc++) {
                            float p = __expf(s[mf][nf][rr*2+cc] - mnew[rr]);
                            s[mf][nf][rr*2+cc] = p;
                            rs[rr] += p;
                        }
                    }
                }
                #pragma unroll
                for (int rr = 0; rr < 2; rr++) {
                    float r2 = rs[rr];
                    r2 += __shfl_xor_sync(0xffffffffu, r2, 1);
                    r2 += __shfl_xor_sync(0xffffffffu, r2, 2);
                    lrow[mf][rr] = lrow[mf][rr]*alpha[rr] + r2;
                    #pragma unroll
                    for (int nf = 0; nf < 8; nf++) {
                        o[mf][nf][rr*2+0] *= alpha[rr];
                        o[mf][nf][rr*2+1] *= alpha[rr];
                    }
                }
                #pragma unroll
                for (int rr = 0; rr < 2; rr++) {
                    int r = wid*32 + mf*16 + (lane >> 2) + rr*8;
                    #pragma unroll
                    for (int nf = 0; nf < 4; nf++) {
                        __half2 h2 = __floats2half2_rn(s[mf][nf][rr*2+0], s[mf][nf][rr*2+1]);
                        *(__half2*)(sP + r*PSH + nf*8 + ((lane & 3) << 1)) = h2;
                    }
                }
            }
            __syncwarp();

            #pragma unroll
            for (int kt = 0; kt < 2; kt++) {
                const int kc = kt*16;
                uint32_t vb[4][4];
                #pragma unroll
                for (int g = 0; g < 4; g++) {
                    int row = sub*32 + kc + l7 + 8*lb3;
                    int col = g*16 + 8*lb4;
                    ldmx4t(vb[g], bV + (uint32_t)(row*SSH + col)*2);
                }
                #pragma unroll
                for (int mf = 0; mf < 2; mf++) {
                    uint32_t pa[4];
                    int row = wid*32 + mf*16 + l7 + 8*lb3;
                    int col = kc + 8*lb4;
                    ldmx4(pa, bP + (uint32_t)(row*PSH + col)*2);
                    #pragma unroll
                    for (int nb = 0; nb < 8; nb++)
                        mma_f16(o[mf][nb], pa, vb[nb>>1][(nb&1)*2], vb[nb>>1][(nb&1)*2+1]);
                }
            }
        }
    }

    const int b = bh >> 4;
    const int h = bh & 15;
    #pragma unroll
    for (int mf = 0; mf < 2; mf++) {
        #pragma unroll
        for (int rr = 0; rr < 2; rr++) {
            float inv = 1.0f / lrow[mf][rr];
            int q = qt*128 + wid*32 + mf*16 + (lane >> 2) + rr*8;
            float* dst = out + ((size_t)b*Tv + q)*Cv + h*Dv;
            #pragma unroll
            for (int nf = 0; nf < 8; nf++) {
                int dd = nf*8 + ((lane & 3) << 1);
                float2 v2;
                v2.x = o[mf][nf][rr*2+0] * inv;
                v2.y = o[mf][nf][rr*2+1] * inv;
                *(float2*)(dst + dd) = v2;
            }
        }
    }
}

extern "C" void kernel_launch(void* const* d_in, const int* in_sizes, int n_in,
                              void* d_out, int out_size) {
    const float* x = (const float*)d_in[0];     // [B,T,C] fp32
    const float* w = (const float*)d_in[1];     // [C,3C] fp32
    float* out = (float*)d_out;                 // [B,T,C] fp32

    prep_x_half<<<(GM*GK/4 + 255)/256, 256>>>((const float4*)x);
    prep_w_half<<<(GK*GN/4 + 255)/256, 256>>>((const float4*)w);

    const int gsmem = (2*ABUF + 2*BBUF) * 2;     // 104448 B
    cudaFuncSetAttribute(qkv_gemm_kernel, cudaFuncAttributeMaxDynamicSharedMemorySize, gsmem);
    qkv_gemm_kernel<<<dim3(GN/256, GM/128), 512, gsmem>>>();

    attn_kernel<<<dim3(Tv/128, Bv*Hv), 128>>>(out);
}

// round 17
// speedup vs baseline: 2.4722x; 1.0722x over previous
#include <cuda_runtime.h>
#include <cuda_fp16.h>
#include <cmath>
#include <cstdint>

#define Bv 4
#define Tv 2048
#define Cv 1024
#define Hv 16
#define Dv 64
#define GM (Bv*Tv)      // 8192
#define GK Cv           // 1024
#define GN (3*Cv)       // 3072
#define SSH 72          // halves stride: attn sQ/sK/sV rows
#define PSH 40          // halves stride: attn sP rows
#define AST 40          // halves stride: gemm A rows (32 k + pad; 80B aligned)
#define BST 136         // halves stride: gemm B rows (128 n + pad; 272B aligned)

// Statics: QKV fp16 (48 MiB) + fp16 X (16 MiB) + fp16 W (6 MiB) = 70 MiB.
// RULE: never pass a __device__ symbol as a host-side kernel argument.
__device__ __align__(16) __half g_Q[Bv*Hv*Tv*Dv];
__device__ __align__(16) __half g_K[Bv*Hv*Tv*Dv];
__device__ __align__(16) __half g_V[Bv*Hv*Tv*Dv];
__device__ __align__(16) __half g_Xh[GM*GK];
__device__ __align__(16) __half g_Wh[GK*GN];

__device__ __forceinline__ void mma_f16(float* c, const uint32_t* a, uint32_t b0, uint32_t b1) {
    asm volatile(
        "mma.sync.aligned.m16n8k16.row.col.f32.f16.f16.f32 "
        "{%0,%1,%2,%3}, {%4,%5,%6,%7}, {%8,%9}, {%0,%1,%2,%3};\n"
        : "+f"(c[0]), "+f"(c[1]), "+f"(c[2]), "+f"(c[3])
        : "r"(a[0]), "r"(a[1]), "r"(a[2]), "r"(a[3]), "r"(b0), "r"(b1));
}

__device__ __forceinline__ uint32_t smem_u32(const void* p) {
    uint32_t a;
    asm("{ .reg .u64 t; cvta.to.shared.u64 t, %1; cvt.u32.u64 %0, t; }" : "=r"(a) : "l"(p));
    return a;
}
__device__ __forceinline__ void ldmx4(uint32_t* r, uint32_t addr) {
    asm volatile("ldmatrix.sync.aligned.m8n8.x4.shared.b16 {%0,%1,%2,%3}, [%4];"
        : "=r"(r[0]), "=r"(r[1]), "=r"(r[2]), "=r"(r[3]) : "r"(addr));
}
__device__ __forceinline__ void ldmx4t(uint32_t* r, uint32_t addr) {
    asm volatile("ldmatrix.sync.aligned.m8n8.x4.trans.shared.b16 {%0,%1,%2,%3}, [%4];"
        : "=r"(r[0]), "=r"(r[1]), "=r"(r[2]), "=r"(r[3]) : "r"(addr));
}
__device__ __forceinline__ uint32_t h2pack(float a, float b) {
    __half2 h = __floats2half2_rn(a, b);
    return *(uint32_t*)&h;
}

// ---------------------------------------------------------------------------
// Prepasses: fp32 -> fp16.  Destination statics referenced in DEVICE code.
// ---------------------------------------------------------------------------
__global__ __launch_bounds__(256) void prep_x_half(const float4* __restrict__ src) {
    int i = blockIdx.x * blockDim.x + threadIdx.x;
    if (i < GM*GK/4) {
        float4 v = src[i];
        uint2 o;
        o.x = h2pack(v.x, v.y);
        o.y = h2pack(v.z, v.w);
        ((uint2*)g_Xh)[i] = o;
    }
}
__global__ __launch_bounds__(256) void prep_w_half(const float4* __restrict__ src) {
    int i = blockIdx.x * blockDim.x + threadIdx.x;
    if (i < GK*GN/4) {
        float4 v = src[i];
        uint2 o;
        o.x = h2pack(v.x, v.y);
        o.y = h2pack(v.z, v.w);
        ((uint2*)g_Wh)[i] = o;
    }
}

// ---------------------------------------------------------------------------
// Kernel 1: QKV projection GEMM — fp16 operands / fp32 accumulate.
// Block tile 128x128, k-tile 32, 256 threads = 8 warps (4m x 2n),
// warp tile 32x64, TWO CTAs per SM (launch_bounds(256,2)) so syncs and
// staging latency of one CTA overlap the other's compute.
// Q is pre-scaled by D^-0.5 = 0.125 in the epilogue (exact, power of 2).
// ---------------------------------------------------------------------------
__global__ __launch_bounds__(256, 2) void qkv_gemm_kernel() {
    __shared__ __half sA[2][128][AST];   // [m][k]
    __shared__ __half sB[2][32][BST];    // [k][n]

    const int tid  = threadIdx.x;
    const int lane = tid & 31;
    const int wid  = tid >> 5;
    const int wm   = wid & 3;            // warp m index 0..3
    const int wn   = wid >> 2;           // warp n index 0..1
    const int m0   = blockIdx.y * 128;
    const int n0   = blockIdx.x * 128;

    const int l7  = lane & 7;
    const int lb3 = (lane >> 3) & 1;
    const int lb4 = (lane >> 4) & 1;

    // staging decomposition (halves): two uint4 per tensor per thread
    const int arow  = tid >> 1;            // 0..127
    const int acolh = (tid & 1) * 16;      // 0 or 16
    const int brow  = tid >> 3;            // 0..31
    const int bcolh = (tid & 7) * 16;      // 0..112

    const __half* Abase = g_Xh + (size_t)(m0 + arow) * GK + acolh;
    const __half* Bbase = g_Wh + (size_t)brow * GN + n0 + bcolh;

    const uint32_t bA = smem_u32(sA);
    const uint32_t bB = smem_u32(sB);

    uint4 ra0 = *(const uint4*)(Abase);
    uint4 ra1 = *(const uint4*)(Abase + 8);
    uint4 rb0 = *(const uint4*)(Bbase);
    uint4 rb1 = *(const uint4*)(Bbase + 8);

    float acc[2][8][4];
    #pragma unroll
    for (int i = 0; i < 2; i++)
        #pragma unroll
        for (int j = 0; j < 8; j++)
            #pragma unroll
            for (int k = 0; k < 4; k++) acc[i][j][k] = 0.f;

    #pragma unroll 1
    for (int kt = 0; kt < GK/32; kt++) {
        const int pb = kt & 1;
        *(uint4*)(&sA[pb][arow][acolh])     = ra0;
        *(uint4*)(&sA[pb][arow][acolh + 8]) = ra1;
        *(uint4*)(&sB[pb][brow][bcolh])     = rb0;
        *(uint4*)(&sB[pb][brow][bcolh + 8]) = rb1;
        __syncthreads();

        if (kt < GK/32 - 1) {
            const __half* an = Abase + (size_t)(kt+1)*32;
            const __half* bn = Bbase + (size_t)(kt+1)*32 * GN;
            ra0 = *(const uint4*)(an);
            ra1 = *(const uint4*)(an + 8);
            rb0 = *(const uint4*)(bn);
            rb1 = *(const uint4*)(bn + 8);
        }

        #pragma unroll
        for (int ks = 0; ks < 2; ks++) {
            const int kk = ks * 16;
            uint32_t af[2][4];
            #pragma unroll
            for (int mf = 0; mf < 2; mf++) {
                int row = wm*32 + mf*16 + l7 + 8*lb3;
                int col = kk + 8*lb4;
                ldmx4(af[mf], bA + (uint32_t)(pb*128*AST + row*AST + col)*2);
            }
            uint32_t bf[4][4];
            #pragma unroll
            for (int g = 0; g < 4; g++) {        // n groups of 16
                int row = kk + l7 + 8*lb3;       // k
                int col = wn*64 + g*16 + 8*lb4;  // n
                ldmx4t(bf[g], bB + (uint32_t)(pb*32*BST + row*BST + col)*2);
            }
            #pragma unroll
            for (int mf = 0; mf < 2; mf++)
                #pragma unroll
                for (int nf = 0; nf < 8; nf++)
                    mma_f16(acc[mf][nf], af[mf], bf[nf>>1][(nf&1)*2], bf[nf>>1][(nf&1)*2+1]);
        }
    }

    // Epilogue: fp16-round + scatter to Q/K/V in [B,H,T,D]; Q pre-scaled.
    #pragma unroll
    for (int mf = 0; mf < 2; mf++) {
        #pragma unroll
        for (int rr = 0; rr < 2; rr++) {
            int m  = m0 + wm*32 + mf*16 + (lane >> 2) + rr*8;
            int bb = m >> 11;
            int tt = m & (Tv - 1);
            #pragma unroll
            for (int nf = 0; nf < 8; nf++) {
                int n  = n0 + wn*64 + nf*8 + ((lane & 3) << 1);
                int s  = n >> 10;
                int cc = n & (Cv - 1);
                int h  = cc >> 6;
                int d  = cc & 63;
                __half* dst = (s == 0) ? g_Q : ((s == 1) ? g_K : g_V);
                float fs = (s == 0) ? 0.125f : 1.0f;
                size_t off = (((size_t)(bb*Hv + h))*Tv + tt)*Dv + d;
                __half2 hv = __floats2half2_rn(acc[mf][nf][rr*2+0]*fs, acc[mf][nf][rr*2+1]*fs);
                *(__half2*)(dst + off) = hv;
            }
        }
    }
}

// ---------------------------------------------------------------------------
// Kernel 2: causal flash attention.  Q arrives pre-scaled by D^-0.5.
// Rescale of O is skipped (warp ballot) when no row max changed.
// ---------------------------------------------------------------------------
__global__ __launch_bounds__(128, 4) void attn_kernel(float* __restrict__ out) {
    __shared__ __half sQ[128*SSH];
    __shared__ __half sK[64*SSH];
    __shared__ __half sV[64*SSH];
    __shared__ __half sP[128*PSH];

    const int tid  = threadIdx.x;
    const int lane = tid & 31;
    const int wid  = tid >> 5;
    const int bh   = blockIdx.y;
    const int qt   = (Tv/128 - 1) - blockIdx.x;           // heavy tiles first

    const __half* Qg = g_Q + (size_t)bh * Tv * Dv;
    const __half* Kg = g_K + (size_t)bh * Tv * Dv;
    const __half* Vg = g_V + (size_t)bh * Tv * Dv;

    const uint32_t bQ = smem_u32(sQ);
    const uint32_t bK = smem_u32(sK);
    const uint32_t bV = smem_u32(sV);
    const uint32_t bP = smem_u32(sP);

    const int l7  = lane & 7;
    const int lb3 = (lane >> 3) & 1;
    const int lb4 = (lane >> 4) & 1;

    {
        const uint4* src = (const uint4*)(Qg + (size_t)(qt*128 + tid)*Dv);
        uint4* dst = (uint4*)(sQ + tid*SSH);
        #pragma unroll
        for (int i = 0; i < 8; i++) dst[i] = src[i];
    }

    float o[2][8][4];
    #pragma unroll
    for (int mf = 0; mf < 2; mf++)
        #pragma unroll
        for (int i = 0; i < 8; i++)
            #pragma unroll
            for (int k = 0; k < 4; k++) o[mf][i][k] = 0.f;
    float mrow[2][2] = {{-INFINITY, -INFINITY}, {-INFINITY, -INFINITY}};
    float lrow[2][2] = {{0.f, 0.f}, {0.f, 0.f}};

    const int jmax = 2*qt + 1;
    #pragma unroll 1
    for (int j = 0; j <= jmax; j++) {
        __syncthreads();
        {
            int r  = tid >> 1;
            int c0 = (tid & 1) * 32;
            const uint4* ks = (const uint4*)(Kg + (size_t)(j*64 + r)*Dv + c0);
            const uint4* vs = (const uint4*)(Vg + (size_t)(j*64 + r)*Dv + c0);
            uint4* kd = (uint4*)(sK + r*SSH + c0);
            uint4* vd = (uint4*)(sV + r*SSH + c0);
            #pragma unroll
            for (int i = 0; i < 4; i++) { kd[i] = ks[i]; vd[i] = vs[i]; }
        }
        __syncthreads();

        const bool maybe_mask = (j >= 2*qt);

        #pragma unroll 1
        for (int sub = 0; sub < 2; sub++) {
            float s[2][4][4];
            #pragma unroll
            for (int mf = 0; mf < 2; mf++)
                #pragma unroll
                for (int i = 0; i < 4; i++)
                    #pragma unroll
                    for (int k = 0; k < 4; k++) s[mf][i][k] = 0.f;

            #pragma unroll
            for (int kt = 0; kt < 4; kt++) {
                const int kc = kt*16;
                uint32_t kb[2][4];
                #pragma unroll
                for (int g = 0; g < 2; g++) {
                    int row = sub*32 + g*16 + l7 + 8*lb4;
                    int col = kc + 8*lb3;
                    ldmx4(kb[g], bK + (uint32_t)(row*SSH + col)*2);
                }
                #pragma unroll
                for (int mf = 0; mf < 2; mf++) {
                    uint32_t qa[4];
                    int row = wid*32 + mf*16 + l7 + 8*lb3;
                    int col = kc + 8*lb4;
                    ldmx4(qa, bQ + (uint32_t)(row*SSH + col)*2);
                    #pragma unroll
                    for (int nf = 0; nf < 4; nf++)
                        mma_f16(s[mf][nf], qa, kb[nf>>1][(nf&1)*2], kb[nf>>1][(nf&1)*2+1]);
                }
            }

            #pragma unroll
            for (int mf = 0; mf < 2; mf++) {
                float mnew[2], alpha[2];
                float mold0 = mrow[mf][0], mold1 = mrow[mf][1];
                #pragma unroll
                for (int rr = 0; rr < 2; rr++) {
                    int qrow = qt*128 + wid*32 + mf*16 + (lane >> 2) + rr*8;
                    float mx = -INFINITY;
                    #pragma unroll
                    for (int nf = 0; nf < 4; nf++) {
                        #pragma unroll
                        for (int cc = 0; cc < 2; cc++) {
                            float v = s[mf][nf][rr*2+cc];      // Q pre-scaled
                            if (maybe_mask) {
                                int kcol = j*64 + sub*32 + nf*8 + ((lane & 3) << 1) + cc;
                                if (kcol > qrow) v = -INFINITY;
                            }
                            s[mf][nf][rr*2+cc] = v;
                            mx = fmaxf(mx, v);
                        }
                    }
                    mx = fmaxf(mx, __shfl_xor_sync(0xffffffffu, mx, 1));
                    mx = fmaxf(mx, __shfl_xor_sync(0xffffffffu, mx, 2));
                    float mn = fmaxf(mrow[mf][rr], mx);
                    mnew[rr]  = mn;
                    alpha[rr] = __expf(mrow[mf][rr] - mn);
                    mrow[mf][rr] = mn;
                }
                float rs[2] = {0.f, 0.f};
                #pragma unroll
                for (int nf = 0; nf < 4; nf++) {
                    #pragma unroll
                    for (int rr = 0; rr < 2; rr++) {
                        #pragma unroll
                        for (int cc = 0; cc < 2; cc++) {
                            float p = __expf(s[mf][nf][rr*2+cc] - mnew[rr]);
                            s[mf][nf][rr*2+cc] = p;
                            rs[rr] += p;
                        }
                    }
                }
                #pragma unroll
                for (int rr = 0; rr < 2; rr++) {
                    float r2 = rs[rr];
                    r2 += __shfl_xor_sync(0xffffffffu, r2, 1);
                    r2 += __shfl_xor_sync(0xffffffffu, r2, 2);
                    lrow[mf][rr] = lrow[mf][rr]*alpha[rr] + r2;
                }
                // skip O rescale if no lane's max changed (alpha == 1 warp-wide)
                bool upd = (mnew[0] > mold0) || (mnew[1] > mold1);
                if (__ballot_sync(0xffffffffu, upd)) {
                    #pragma unroll
                    for (int rr = 0; rr < 2; rr++) {
                        #pragma unroll
                        for (int nf = 0; nf < 8; nf++) {
                            o[mf][nf][rr*2+0] *= alpha[rr];
                            o[mf][nf][rr*2+1] *= alpha[rr];
                        }
                    }
                }
                #pragma unroll
                for (int rr = 0; rr < 2; rr++) {
                    int r = wid*32 + mf*16 + (lane >> 2) + rr*8;
                    #pragma unroll
                    for (int nf = 0; nf < 4; nf++) {
                        __half2 h2 = __floats2half2_rn(s[mf][nf][rr*2+0], s[mf][nf][rr*2+1]);
                        *(__half2*)(sP + r*PSH + nf*8 + ((lane & 3) << 1)) = h2;
                    }
                }
            }
            __syncwarp();

            #pragma unroll
            for (int kt = 0; kt < 2; kt++) {
                const int kc = kt*16;
                uint32_t vb[4][4];
                #pragma unroll
                for (int g = 0; g < 4; g++) {
                    int row = sub*32 + kc + l7 + 8*lb3;
                    int col = g*16 + 8*lb4;
                    ldmx4t(vb[g], bV + (uint32_t)(row*SSH + col)*2);
                }
                #pragma unroll
                for (int mf = 0; mf < 2; mf++) {
                    uint32_t pa[4];
                    int row = wid*32 + mf*16 + l7 + 8*lb3;
                    int col = kc + 8*lb4;
                    ldmx4(pa, bP + (uint32_t)(row*PSH + col)*2);
                    #pragma unroll
                    for (int nb = 0; nb < 8; nb++)
                        mma_f16(o[mf][nb], pa, vb[nb>>1][(nb&1)*2], vb[nb>>1][(nb&1)*2+1]);
                }
            }
        }
    }

    const int b = bh >> 4;
    const int h = bh & 15;
    #pragma unroll
    for (int mf = 0; mf < 2; mf++) {
        #pragma unroll
        for (int rr = 0; rr < 2; rr++) {
            float inv = 1.0f / lrow[mf][rr];
            int q = qt*128 + wid*32 + mf*16 + (lane >> 2) + rr*8;
            float* dst = out + ((size_t)b*Tv + q)*Cv + h*Dv;
            #pragma unroll
            for (int nf = 0; nf < 8; nf++) {
                int dd = nf*8 + ((lane & 3) << 1);
                float2 v2;
                v2.x = o[mf][nf][rr*2+0] * inv;
                v2.y = o[mf][nf][rr*2+1] * inv;
                *(float2*)(dst + dd) = v2;
            }
        }
    }
}

extern "C" void kernel_launch(void* const* d_in, const int* in_sizes, int n_in,
                              void* d_out, int out_size) {
    const float* x = (const float*)d_in[0];     // [B,T,C] fp32
    const float* w = (const float*)d_in[1];     // [C,3C] fp32
    float* out = (float*)d_out;                 // [B,T,C] fp32

    prep_x_half<<<(GM*GK/4 + 255)/256, 256>>>((const float4*)x);
    prep_w_half<<<(GK*GN/4 + 255)/256, 256>>>((const float4*)w);

    qkv_gemm_kernel<<<dim3(GN/128, GM/128), 256>>>();

    attn_kernel<<<dim3(Tv/128, Bv*Hv), 128>>>(out);
}